// round 14
// baseline (speedup 1.0000x reference)
#include <cuda_runtime.h>
#include <cuda_bf16.h>
#include <cstdint>

// ---------------------------------------------------------------------------
// DANet PAM+CAM fused pipeline.  B=4, C=64, H=W=64, N=4096, Cq=8.
// PAM attention: flash kernel (256 thr, 8 warps x 16 rows, 2 warps/SMSP),
// P*V via 3-term bf16 split on m16n8k16 mma:
//   p = pH + pL/256, v = vH + vL/256  (bf16 hi + bf16 residual*2^8)
//   acc += pH*vH ; accx += pL*vH + pH*vL ; o = (acc + accx/256)/rowsum.
// K stored in smem pre-duplicated as fp32 pairs (feeds FFMA2 directly,
// removing 256 pack MOVs per warp-tile).
// ---------------------------------------------------------------------------

#define B_SZ 4
#define C_SZ 64
#define N_SZ 4096
#define LOG2E 1.4426950408889634f

typedef unsigned long long ull;

// Scratch (allocation-free rule: device globals)
__device__ float g_q[B_SZ * 8 * N_SZ];      // [b][d][n]
__device__ float g_k[B_SZ * 8 * N_SZ];      // [b][d][n]
__device__ __align__(16) __nv_bfloat16 g_vh[B_SZ * C_SZ * N_SZ]; // v_hi
__device__ __align__(16) __nv_bfloat16 g_vl[B_SZ * C_SZ * N_SZ]; // (v-vh)*256
__device__ float g_o[B_SZ * C_SZ * N_SZ];   // PAM attn out, later CAM out
__device__ float g_y[B_SZ * C_SZ * N_SZ];   // PAM residual output y
__device__ float g_ec[B_SZ * C_SZ * C_SZ];  // CAM gram (energy)
__device__ float g_kA[C_SZ];                // folded BN scale
__device__ float g_kB[C_SZ];                // folded BN shift

// ---- helpers ---------------------------------------------------------------
__device__ __forceinline__ ull pack2(float a, float b) {
    ull r; asm("mov.b64 %0, {%1,%2};" : "=l"(r) : "f"(a), "f"(b)); return r;
}
__device__ __forceinline__ void unpack2(ull v, float& a, float& b) {
    asm("mov.b64 {%0,%1}, %2;" : "=f"(a), "=f"(b) : "l"(v));
}
__device__ __forceinline__ void fma2(ull& d, ull a, ull b) {
    asm("fma.rn.f32x2 %0, %1, %2, %0;" : "+l"(d) : "l"(a), "l"(b));
}
__device__ __forceinline__ float ex2f(float x) {
    float y; asm("ex2.approx.f32 %0, %1;" : "=f"(y) : "f"(x)); return y;
}
// pack {lo, hi} floats into bf16x2 (PTX: first source -> upper 16 bits)
__device__ __forceinline__ uint32_t bf16x2(float lo, float hi) {
    uint32_t r; asm("cvt.rn.bf16x2.f32 %0, %1, %2;" : "=r"(r) : "f"(hi), "f"(lo));
    return r;
}
// exact bf16x2 -> two floats (bit shift, no precision loss)
__device__ __forceinline__ void b2f2(uint32_t h, float& lo, float& hi) {
    lo = __uint_as_float(h << 16);
    hi = __uint_as_float(h & 0xffff0000u);
}
__device__ __forceinline__ uint32_t cvta_smem(const void* p) {
    uint32_t a;
    asm("{ .reg .u64 t; cvta.to.shared.u64 t, %1; cvt.u32.u64 %0, t; }"
        : "=r"(a) : "l"(p));
    return a;
}
__device__ __forceinline__ void cp16(uint32_t dst, const void* src) {
    asm volatile("cp.async.ca.shared.global [%0], [%1], 16;"
                 :: "r"(dst), "l"(src) : "memory");
}
#define CP_COMMIT() asm volatile("cp.async.commit_group;" ::: "memory")
#define CP_WAIT0()  asm volatile("cp.async.wait_group 0;" ::: "memory")

// m16n8k16 bf16 mma, fp32 accumulate: D += A * B
__device__ __forceinline__ void mma_bf16(float* d, const uint32_t* a,
                                         uint32_t b0, uint32_t b1) {
    asm volatile(
        "mma.sync.aligned.m16n8k16.row.col.f32.bf16.bf16.f32 "
        "{%0,%1,%2,%3}, {%4,%5,%6,%7}, {%8,%9}, {%0,%1,%2,%3};"
        : "+f"(d[0]), "+f"(d[1]), "+f"(d[2]), "+f"(d[3])
        : "r"(a[0]), "r"(a[1]), "r"(a[2]), "r"(a[3]), "r"(b0), "r"(b1));
}

// ===========================================================================
// K1: fused QKV projection.  256 threads, 2 threads per (b, n) column.
// V stored as bf16 hi + bf16 residual*256 (consumed only by the bf16 mma).
// ===========================================================================
__global__ __launch_bounds__(256) void qkv_kernel(
    const float* __restrict__ x,
    const float* __restrict__ Wq, const float* __restrict__ bq,
    const float* __restrict__ Wk, const float* __restrict__ bk,
    const float* __restrict__ Wv, const float* __restrict__ bv)
{
    __shared__ float Ws[80 * 64];
    __shared__ float bs[80];
    const int t = threadIdx.x;
    const int half = t >> 7, tl = t & 127;
    const int b = blockIdx.x >> 5;
    const int n = ((blockIdx.x & 31) << 7) + tl;

    for (int i = t; i < 512; i += 256)  Ws[i]        = Wq[i];
    for (int i = t; i < 512; i += 256)  Ws[512 + i]  = Wk[i];
    for (int i = t; i < 4096; i += 256) Ws[1024 + i] = Wv[i];
    if (t < 80) bs[t] = (t < 8) ? bq[t] : (t < 16 ? bk[t - 8] : bv[t - 16]);
    __syncthreads();

    const int ob = half * 40;
    float acc[40];
#pragma unroll
    for (int o = 0; o < 40; o++) acc[o] = bs[ob + o];

    const float* xb = x + (b << 6) * N_SZ + n;
    for (int c = 0; c < 64; c += 4) {
        float x0 = xb[c * N_SZ];
        float x1 = xb[(c + 1) * N_SZ];
        float x2 = xb[(c + 2) * N_SZ];
        float x3 = xb[(c + 3) * N_SZ];
#pragma unroll
        for (int o = 0; o < 40; o++) {
            float4 w = *(const float4*)(Ws + ((ob + o) << 6) + c);
            acc[o] = fmaf(w.x, x0, fmaf(w.y, x1, fmaf(w.z, x2, fmaf(w.w, x3, acc[o]))));
        }
    }
    if (half == 0) {
#pragma unroll
        for (int o = 0; o < 8; o++)  g_q[((b << 3) + o) * N_SZ + n] = acc[o];
#pragma unroll
        for (int o = 0; o < 8; o++)  g_k[((b << 3) + o) * N_SZ + n] = acc[8 + o];
#pragma unroll
        for (int o = 0; o < 24; o++) {
            float v = acc[16 + o];
            __nv_bfloat16 vh = __float2bfloat16(v);
            g_vh[((b << 6) + o) * N_SZ + n] = vh;
            g_vl[((b << 6) + o) * N_SZ + n] =
                __float2bfloat16((v - __bfloat162float(vh)) * 256.f);
        }
    } else {
#pragma unroll
        for (int o = 0; o < 40; o++) {
            float v = acc[o];
            __nv_bfloat16 vh = __float2bfloat16(v);
            g_vh[((b << 6) + 24 + o) * N_SZ + n] = vh;
            g_vl[((b << 6) + 24 + o) * N_SZ + n] =
                __float2bfloat16((v - __bfloat162float(vh)) * 256.f);
        }
    }
}

// ===========================================================================
// K2: flash attention.  128 CTAs (b = bx>>5, m-tile = bx&31), 256 threads.
//   8 warps, each owns 16 query rows (2 warps per SMSP).
//   K stored as duplicated fp32 pairs (ull), pitch 10 (aligned + bank-clean).
//   S = QK^T on FFMA2; p = 2^(s*log2e).  P*V: 3-stream bf16 m16n8k16 mma.
// SMEM: vh[2][64][136]bf + vl[2][64][136]bf + k[2][128][10]ull = 90112 B.
// ===========================================================================
#define VP_H   136                    // bf16 pitch per V row
#define VBUF_H (64 * VP_H)            // bf16 elems per V buffer
#define KP_U   10                     // ull pitch per key row
#define KBUF_U (128 * KP_U)
#define FLASH_SMEM (4 * VBUF_H * 2 + 2 * KBUF_U * 8)

__global__ __launch_bounds__(256, 1) void flash_kernel()
{
    extern __shared__ char smraw[];
    __nv_bfloat16* vh_s = (__nv_bfloat16*)smraw;        // [2][64][136]
    __nv_bfloat16* vl_s = vh_s + 2 * VBUF_H;            // [2][64][136]
    ull*           k_s  = (ull*)(vl_s + 2 * VBUF_H);    // [2][128][10]

    const int t    = threadIdx.x;
    const int lane = t & 31;
    const int w    = t >> 5;           // 0..7
    const int g    = lane >> 2;
    const int tg   = lane & 3;
    const int m0w  = w << 4;           // 16 rows per warp
    const int b    = blockIdx.x >> 5;
    const int m0g  = (blockIdx.x & 31) << 7;

    const uint32_t smb_vh = cvta_smem(vh_s);
    const uint32_t smb_vl = cvta_smem(vl_s);
    const float* gq = g_q + (b << 3) * N_SZ;
    const float* gk = g_k + (b << 3) * N_SZ;
    const __nv_bfloat16* gvh = g_vh + (b << 6) * N_SZ;
    const __nv_bfloat16* gvl = g_vl + (b << 6) * N_SZ;

    // Q pairs (row m0w+g, row m0w+g+8), scaled by log2(e)
    ull qp2[8];
#pragma unroll
    for (int d = 0; d < 8; d++) {
        float qa = gq[d * N_SZ + m0g + m0w + g] * LOG2E;
        float qb = gq[d * N_SZ + m0g + m0w + g + 8] * LOG2E;
        qp2[d] = pack2(qa, qb);
    }

    float acc[8][4], accx[8][4];
#pragma unroll
    for (int cs = 0; cs < 8; cs++)
#pragma unroll
        for (int j = 0; j < 4; j++) { acc[cs][j] = 0.f; accx[cs][j] = 0.f; }
    float rs[2] = {0.f, 0.f};

    float kreg[8];

    // prologue: tile 0 (V via cp.async from all 256 threads; K by warps 0-3)
#pragma unroll
    for (int j = 0; j < 4; j++) {
        int i = t + (j << 8);          // [0, 1024)
        int c = i >> 4, jj = i & 15;
        cp16(smb_vh + c * (VP_H * 2) + jj * 16, gvh + c * N_SZ + jj * 8);
        cp16(smb_vl + c * (VP_H * 2) + jj * 16, gvl + c * N_SZ + jj * 8);
    }
    CP_COMMIT();
    if (w < 4) {
#pragma unroll
        for (int d = 0; d < 8; d++) kreg[d] = gk[d * N_SZ + t];
        ull* kd = k_s + t * KP_U;
#pragma unroll
        for (int d = 0; d < 8; d += 2) {
            longlong2 p;
            p.x = (long long)pack2(kreg[d], kreg[d]);
            p.y = (long long)pack2(kreg[d + 1], kreg[d + 1]);
            *(longlong2*)(kd + d) = p;
        }
    }

#pragma unroll 1
    for (int nt = 0; nt < 32; nt++) {
        const int buf = nt & 1;
        CP_WAIT0();
        __syncthreads();

        if (nt < 31) {
            const int n1 = (nt + 1) << 7;
#pragma unroll
            for (int j = 0; j < 4; j++) {
                int i = t + (j << 8);
                int c = i >> 4, jj = i & 15;
                cp16(smb_vh + ((buf ^ 1) * VBUF_H + c * VP_H) * 2 + jj * 16,
                     gvh + c * N_SZ + n1 + jj * 8);
                cp16(smb_vl + ((buf ^ 1) * VBUF_H + c * VP_H) * 2 + jj * 16,
                     gvl + c * N_SZ + n1 + jj * 8);
            }
            CP_COMMIT();
            if (w < 4) {
#pragma unroll
                for (int d = 0; d < 8; d++) kreg[d] = gk[d * N_SZ + n1 + t];
            }
        }

        // ---- compute tile nt ----
        const ull* kb = k_s + buf * KBUF_U;
        const __nv_bfloat16* vhb = vh_s + buf * VBUF_H;
        const __nv_bfloat16* vlb = vl_s + buf * VBUF_H;
#pragma unroll
        for (int kg = 0; kg < 8; kg++) {
            const int base = kg << 4;
            // keys j0..j3 = base + {2tg, 2tg+1, 2tg+8, 2tg+9}
            const ull* kp0 = kb + (base + 2 * tg) * KP_U;

            // s[col]: packed over rows {m0w+g, m0w+g+8}
            ull s0 = 0ull, s1 = 0ull, s2 = 0ull, s3 = 0ull;
#pragma unroll
            for (int dd = 0; dd < 8; dd += 2) {
                longlong2 a0 = *(const longlong2*)(kp0 + dd);
                longlong2 a1 = *(const longlong2*)(kp0 + KP_U + dd);
                longlong2 a2 = *(const longlong2*)(kp0 + 8 * KP_U + dd);
                longlong2 a3 = *(const longlong2*)(kp0 + 9 * KP_U + dd);
                fma2(s0, qp2[dd], (ull)a0.x); fma2(s0, qp2[dd + 1], (ull)a0.y);
                fma2(s1, qp2[dd], (ull)a1.x); fma2(s1, qp2[dd + 1], (ull)a1.y);
                fma2(s2, qp2[dd], (ull)a2.x); fma2(s2, qp2[dd + 1], (ull)a2.y);
                fma2(s3, qp2[dd], (ull)a3.x); fma2(s3, qp2[dd + 1], (ull)a3.y);
            }

            float p0x, p0y, p1x, p1y, p2x, p2y, p3x, p3y;
            unpack2(s0, p0x, p0y); unpack2(s1, p1x, p1y);
            unpack2(s2, p2x, p2y); unpack2(s3, p3x, p3y);
            p0x = ex2f(p0x); p0y = ex2f(p0y);
            p1x = ex2f(p1x); p1y = ex2f(p1y);
            p2x = ex2f(p2x); p2y = ex2f(p2y);
            p3x = ex2f(p3x); p3y = ex2f(p3y);
            rs[0] += p0x + p1x + p2x + p3x;
            rs[1] += p0y + p1y + p2y + p3y;

            // A fragments: a0={A[g][2tg],A[g][2tg+1]}, a1=rows g+8,
            //              a2/a3 = cols +8.
            uint32_t aH[4], aL[4];
            aH[0] = bf16x2(p0x, p1x);
            aH[1] = bf16x2(p0y, p1y);
            aH[2] = bf16x2(p2x, p3x);
            aH[3] = bf16x2(p2y, p3y);
            float h0, h1;
            b2f2(aH[0], h0, h1);
            aL[0] = bf16x2((p0x - h0) * 256.f, (p1x - h1) * 256.f);
            b2f2(aH[1], h0, h1);
            aL[1] = bf16x2((p0y - h0) * 256.f, (p1y - h1) * 256.f);
            b2f2(aH[2], h0, h1);
            aL[2] = bf16x2((p2x - h0) * 256.f, (p3x - h1) * 256.f);
            b2f2(aH[3], h0, h1);
            aL[3] = bf16x2((p2y - h0) * 256.f, (p3y - h1) * 256.f);

#pragma unroll
            for (int cs = 0; cs < 8; cs++) {
                const int off = ((cs << 3) + g) * VP_H + base + 2 * tg;
                uint32_t bh0 = *(const uint32_t*)(vhb + off);
                uint32_t bh1 = *(const uint32_t*)(vhb + off + 8);
                uint32_t bl0 = *(const uint32_t*)(vlb + off);
                uint32_t bl1 = *(const uint32_t*)(vlb + off + 8);
                mma_bf16(acc[cs],  aH, bh0, bh1);
                mma_bf16(accx[cs], aL, bh0, bh1);
                mma_bf16(accx[cs], aH, bl0, bl1);
            }
        }

        if (nt < 31 && w < 4) {
            ull* kd = k_s + (buf ^ 1) * KBUF_U + t * KP_U;
#pragma unroll
            for (int d = 0; d < 8; d += 2) {
                longlong2 p;
                p.x = (long long)pack2(kreg[d], kreg[d]);
                p.y = (long long)pack2(kreg[d + 1], kreg[d + 1]);
                *(longlong2*)(kd + d) = p;
            }
        }
    }

    // complete row sums across the 4 lanes of each quad, normalize, store
#pragma unroll
    for (int j = 0; j < 2; j++) {
        rs[j] += __shfl_xor_sync(0xffffffffu, rs[j], 1);
        rs[j] += __shfl_xor_sync(0xffffffffu, rs[j], 2);
        rs[j] = 1.f / rs[j];
    }
    const float inv256 = 1.f / 256.f;
    float* go = g_o + (b << 6) * N_SZ;
    const int m = m0g + m0w + g;
#pragma unroll
    for (int cs = 0; cs < 8; cs++) {
        const int c = (cs << 3) + (tg << 1);
        go[c * N_SZ + m]           = fmaf(accx[cs][0], inv256, acc[cs][0]) * rs[0];
        go[(c + 1) * N_SZ + m]     = fmaf(accx[cs][1], inv256, acc[cs][1]) * rs[0];
        go[c * N_SZ + m + 8]       = fmaf(accx[cs][2], inv256, acc[cs][2]) * rs[1];
        go[(c + 1) * N_SZ + m + 8] = fmaf(accx[cs][3], inv256, acc[cs][3]) * rs[1];
    }
}

// ===========================================================================
// K3/K7: fold training-mode BN of (gamma * g_o) into per-channel A, B.
// ===========================================================================
__global__ void bnstats_kernel(const float* __restrict__ w,
                               const float* __restrict__ bb,
                               const float* __restrict__ gamma)
{
    __shared__ float s1s[256], s2s[256];
    const int c = blockIdx.x, t = threadIdx.x;
    float s1 = 0.f, s2 = 0.f;
    const float4* o4 = (const float4*)g_o;
    for (int i = t; i < 4096; i += 256) {
        int b = i >> 10, n4 = i & 1023;
        float4 v = o4[(((b << 6) + c) << 10) + n4];
        s1 += v.x + v.y + v.z + v.w;
        s2 += v.x * v.x + v.y * v.y + v.z * v.z + v.w * v.w;
    }
    s1s[t] = s1; s2s[t] = s2;
    __syncthreads();
    for (int off = 128; off > 0; off >>= 1) {
        if (t < off) { s1s[t] += s1s[t + off]; s2s[t] += s2s[t + off]; }
        __syncthreads();
    }
    if (t == 0) {
        const float gmm = gamma[0];
        const float inv_n = 1.f / (float)(B_SZ * N_SZ);
        float mean = gmm * s1s[0] * inv_n;
        float ex2v = gmm * gmm * s2s[0] * inv_n;
        float var  = ex2v - mean * mean;
        float r    = rsqrtf(var + 1e-5f);
        float A    = w[c] * r;
        g_kA[c] = A * gmm;
        g_kB[c] = bb[c] - mean * A;
    }
}

// K4: y = A*o + B + x ; zero CAM gram accumulator  (float4)
__global__ void pam_resid_kernel(const float4* __restrict__ x4)
{
    int i = blockIdx.x * 256 + threadIdx.x;   // 262144 float4
    int c = (i >> 10) & 63;
    float4 o = ((const float4*)g_o)[i];
    float4 xx = x4[i];
    float A = g_kA[c], Bc = g_kB[c];
    float4 r;
    r.x = fmaf(o.x, A, Bc) + xx.x;
    r.y = fmaf(o.y, A, Bc) + xx.y;
    r.z = fmaf(o.z, A, Bc) + xx.z;
    r.w = fmaf(o.w, A, Bc) + xx.w;
    ((float4*)g_y)[i] = r;
    if (i < 4096) ((float4*)g_ec)[i] = make_float4(0.f, 0.f, 0.f, 0.f);
}

// K5: CAM gram via partial tiles + atomics (128-column tiles, proven best)
__global__ __launch_bounds__(256) void gram_kernel()
{
    __shared__ float yt[64 * 129];
    const int b = blockIdx.y;
    const int n0 = blockIdx.x << 7;
    const int t = threadIdx.x;
    for (int i = t; i < 8192; i += 256) {
        int c = i >> 7, j = i & 127;
        yt[c * 129 + j] = g_y[((b << 6) + c) * N_SZ + n0 + j];
    }
    __syncthreads();
    const int c0 = (t >> 4) << 2;
    const int d0 = (t & 15) << 2;
    float a[4][4] = {};
    for (int n = 0; n < 128; n++) {
        float yc0 = yt[c0 * 129 + n],       yc1 = yt[(c0 + 1) * 129 + n];
        float yc2 = yt[(c0 + 2) * 129 + n], yc3 = yt[(c0 + 3) * 129 + n];
        float yd0 = yt[d0 * 129 + n],       yd1 = yt[(d0 + 1) * 129 + n];
        float yd2 = yt[(d0 + 2) * 129 + n], yd3 = yt[(d0 + 3) * 129 + n];
        a[0][0] += yc0 * yd0; a[0][1] += yc0 * yd1; a[0][2] += yc0 * yd2; a[0][3] += yc0 * yd3;
        a[1][0] += yc1 * yd0; a[1][1] += yc1 * yd1; a[1][2] += yc1 * yd2; a[1][3] += yc1 * yd3;
        a[2][0] += yc2 * yd0; a[2][1] += yc2 * yd1; a[2][2] += yc2 * yd2; a[2][3] += yc2 * yd3;
        a[3][0] += yc3 * yd0; a[3][1] += yc3 * yd1; a[3][2] += yc3 * yd2; a[3][3] += yc3 * yd3;
    }
    float* e = g_ec + (b << 12);
#pragma unroll
    for (int ii = 0; ii < 4; ii++)
#pragma unroll
        for (int jj = 0; jj < 4; jj++)
            atomicAdd(e + (c0 + ii) * 64 + d0 + jj, a[ii][jj]);
}

// K6: CAM softmax + apply, fused.  out_c = softmax(-energy) @ y  -> g_o.
__global__ __launch_bounds__(256) void cam_apply_kernel()
{
    __shared__ float As[4096];
    const int t = threadIdx.x, half = t >> 7, tl = t & 127;
    const int b = blockIdx.x >> 5;
    const int n = ((blockIdx.x & 31) << 7) + tl;
    for (int i = t; i < 4096; i += 256) As[i] = g_ec[(b << 12) + i];
    __syncthreads();
    if (t < 64) {
        float* e = As + (t << 6);
        float emin = 3.0e38f;
#pragma unroll
        for (int j = 0; j < 64; j++) emin = fminf(emin, e[(j + t) & 63]);
        float sum = 0.f;
#pragma unroll
        for (int j = 0; j < 64; j++) {
            int d = (j + t) & 63;
            float v = __expf(emin - e[d]);
            e[d] = v;
            sum += v;
        }
        const float inv = 1.f / sum;
#pragma unroll
        for (int j = 0; j < 64; j++) e[(j + t) & 63] *= inv;
    }
    __syncthreads();
    float acc[32];
#pragma unroll
    for (int c = 0; c < 32; c++) acc[c] = 0.f;
    const float* yb = g_y + (b << 6) * N_SZ + n;
    const int ch0 = half << 5;
    for (int d = 0; d < 64; d += 4) {
        float y0 = yb[d * N_SZ], y1 = yb[(d + 1) * N_SZ];
        float y2 = yb[(d + 2) * N_SZ], y3 = yb[(d + 3) * N_SZ];
#pragma unroll
        for (int c = 0; c < 32; c++) {
            float4 w = *(const float4*)(As + ((ch0 + c) << 6) + d);
            acc[c] = fmaf(w.x, y0, fmaf(w.y, y1, fmaf(w.z, y2, fmaf(w.w, y3, acc[c]))));
        }
    }
    float* ob = g_o + ((b << 6) + ch0) * N_SZ + n;
#pragma unroll
    for (int c = 0; c < 32; c++) ob[c * N_SZ] = acc[c];
}

// K8: final = A*out_c + B + y  (float4)
__global__ void final_kernel(float4* __restrict__ out4)
{
    int i = blockIdx.x * 256 + threadIdx.x;
    int c = (i >> 10) & 63;
    float4 o = ((const float4*)g_o)[i];
    float4 yy = ((const float4*)g_y)[i];
    float A = g_kA[c], Bc = g_kB[c];
    float4 r;
    r.x = fmaf(o.x, A, Bc) + yy.x;
    r.y = fmaf(o.y, A, Bc) + yy.y;
    r.z = fmaf(o.z, A, Bc) + yy.z;
    r.w = fmaf(o.w, A, Bc) + yy.w;
    out4[i] = r;
}

// ===========================================================================
extern "C" void kernel_launch(void* const* d_in, const int* in_sizes, int n_in,
                              void* d_out, int out_size)
{
    const float* x       = (const float*)d_in[0];
    const float* Wq      = (const float*)d_in[1];
    const float* bq      = (const float*)d_in[2];
    const float* Wk      = (const float*)d_in[3];
    const float* bk      = (const float*)d_in[4];
    const float* Wv      = (const float*)d_in[5];
    const float* bv      = (const float*)d_in[6];
    const float* gamma_p = (const float*)d_in[7];
    const float* bnp_w   = (const float*)d_in[8];
    const float* bnp_b   = (const float*)d_in[9];
    const float* gamma_c = (const float*)d_in[10];
    const float* bnc_w   = (const float*)d_in[11];
    const float* bnc_b   = (const float*)d_in[12];
    float4* out = (float4*)d_out;

    cudaFuncSetAttribute(flash_kernel,
                         cudaFuncAttributeMaxDynamicSharedMemorySize,
                         FLASH_SMEM);

    qkv_kernel<<<128, 256>>>(x, Wq, bq, Wk, bk, Wv, bv);
    flash_kernel<<<128, 256, FLASH_SMEM>>>();
    bnstats_kernel<<<64, 256>>>(bnp_w, bnp_b, gamma_p);
    pam_resid_kernel<<<1024, 256>>>((const float4*)x);
    gram_kernel<<<dim3(32, 4), 256>>>();
    cam_apply_kernel<<<128, 256>>>();
    bnstats_kernel<<<64, 256>>>(bnc_w, bnc_b, gamma_c);
    final_kernel<<<1024, 256>>>(out);
}

// round 15
// speedup vs baseline: 1.1242x; 1.1242x over previous
#include <cuda_runtime.h>
#include <cuda_bf16.h>
#include <cstdint>

// ---------------------------------------------------------------------------
// DANet PAM+CAM fused pipeline.  B=4, C=64, H=W=64, N=4096, Cq=8.
// PAM attention: flash kernel (256 thr, 8 warps x 16 rows, 2 warps/SMSP),
// P*V via 3-term bf16 split on m16n8k16 mma:
//   p = pH + pL/256, v = vH + vL/256  (bf16 hi + bf16 residual*2^8)
//   acc += pH*vH ; accx += pL*vH + pH*vL ; o = (acc + accx/256)/rowsum.
// bf16 spans fp32 exponents: no shift, no clamp, no subnormal issues.
// ---------------------------------------------------------------------------

#define B_SZ 4
#define C_SZ 64
#define N_SZ 4096
#define LOG2E 1.4426950408889634f

typedef unsigned long long ull;

// Scratch (allocation-free rule: device globals)
__device__ float g_q[B_SZ * 8 * N_SZ];      // [b][d][n]
__device__ float g_k[B_SZ * 8 * N_SZ];      // [b][d][n]
__device__ __align__(16) __nv_bfloat16 g_vh[B_SZ * C_SZ * N_SZ]; // v_hi
__device__ __align__(16) __nv_bfloat16 g_vl[B_SZ * C_SZ * N_SZ]; // (v-vh)*256
__device__ float g_o[B_SZ * C_SZ * N_SZ];   // PAM attn out, later CAM out
__device__ float g_y[B_SZ * C_SZ * N_SZ];   // PAM residual output y
__device__ float g_ec[B_SZ * C_SZ * C_SZ];  // CAM gram (energy)
__device__ float g_kA[C_SZ];                // folded BN scale
__device__ float g_kB[C_SZ];                // folded BN shift

// ---- helpers ---------------------------------------------------------------
__device__ __forceinline__ ull pack2(float a, float b) {
    ull r; asm("mov.b64 %0, {%1,%2};" : "=l"(r) : "f"(a), "f"(b)); return r;
}
__device__ __forceinline__ void unpack2(ull v, float& a, float& b) {
    asm("mov.b64 {%0,%1}, %2;" : "=f"(a), "=f"(b) : "l"(v));
}
__device__ __forceinline__ void fma2(ull& d, ull a, ull b) {
    asm("fma.rn.f32x2 %0, %1, %2, %0;" : "+l"(d) : "l"(a), "l"(b));
}
__device__ __forceinline__ float ex2f(float x) {
    float y; asm("ex2.approx.f32 %0, %1;" : "=f"(y) : "f"(x)); return y;
}
// pack {lo, hi} floats into bf16x2 (PTX: first source -> upper 16 bits)
__device__ __forceinline__ uint32_t bf16x2(float lo, float hi) {
    uint32_t r; asm("cvt.rn.bf16x2.f32 %0, %1, %2;" : "=r"(r) : "f"(hi), "f"(lo));
    return r;
}
// exact bf16x2 -> two floats (bit shift, no precision loss)
__device__ __forceinline__ void b2f2(uint32_t h, float& lo, float& hi) {
    lo = __uint_as_float(h << 16);
    hi = __uint_as_float(h & 0xffff0000u);
}
__device__ __forceinline__ uint32_t cvta_smem(const void* p) {
    uint32_t a;
    asm("{ .reg .u64 t; cvta.to.shared.u64 t, %1; cvt.u32.u64 %0, t; }"
        : "=r"(a) : "l"(p));
    return a;
}
__device__ __forceinline__ void cp16(uint32_t dst, const void* src) {
    asm volatile("cp.async.ca.shared.global [%0], [%1], 16;"
                 :: "r"(dst), "l"(src) : "memory");
}
#define CP_COMMIT() asm volatile("cp.async.commit_group;" ::: "memory")
#define CP_WAIT0()  asm volatile("cp.async.wait_group 0;" ::: "memory")

// m16n8k16 bf16 mma, fp32 accumulate: D += A * B
__device__ __forceinline__ void mma_bf16(float* d, const uint32_t* a,
                                         uint32_t b0, uint32_t b1) {
    asm volatile(
        "mma.sync.aligned.m16n8k16.row.col.f32.bf16.bf16.f32 "
        "{%0,%1,%2,%3}, {%4,%5,%6,%7}, {%8,%9}, {%0,%1,%2,%3};"
        : "+f"(d[0]), "+f"(d[1]), "+f"(d[2]), "+f"(d[3])
        : "r"(a[0]), "r"(a[1]), "r"(a[2]), "r"(a[3]), "r"(b0), "r"(b1));
}

// ===========================================================================
// K1: fused QKV projection.  256 CTAs (64-column tiles), 256 threads,
// 4 threads per (b, n) column (20 outputs each).  x tile staged in smem.
// V stored as bf16 hi + bf16 residual*256.
// ===========================================================================
__global__ __launch_bounds__(256) void qkv_kernel(
    const float* __restrict__ x,
    const float* __restrict__ Wq, const float* __restrict__ bq,
    const float* __restrict__ Wk, const float* __restrict__ bk,
    const float* __restrict__ Wv, const float* __restrict__ bv)
{
    __shared__ float Ws[80 * 64];
    __shared__ float bs[80];
    __shared__ float xs[64 * 65];
    const int t  = threadIdx.x;
    const int b  = blockIdx.x >> 6;
    const int n0 = (blockIdx.x & 63) << 6;
    const int nl = t & 63;
    const int og = t >> 6;              // 0..3
    const int n  = n0 + nl;

    for (int i = t; i < 512; i += 256)  Ws[i]        = Wq[i];
    for (int i = t; i < 512; i += 256)  Ws[512 + i]  = Wk[i];
    for (int i = t; i < 4096; i += 256) Ws[1024 + i] = Wv[i];
    if (t < 80) bs[t] = (t < 8) ? bq[t] : (t < 16 ? bk[t - 8] : bv[t - 16]);
    for (int i = t; i < 4096; i += 256) {
        int c = i >> 6, j = i & 63;
        xs[c * 65 + j] = x[((b << 6) + c) * N_SZ + n0 + j];
    }
    __syncthreads();

    const int ob = og * 20;
    float acc[20];
#pragma unroll
    for (int o = 0; o < 20; o++) acc[o] = bs[ob + o];

    for (int c = 0; c < 64; c += 4) {
        float x0 = xs[c * 65 + nl];
        float x1 = xs[(c + 1) * 65 + nl];
        float x2 = xs[(c + 2) * 65 + nl];
        float x3 = xs[(c + 3) * 65 + nl];
#pragma unroll
        for (int o = 0; o < 20; o++) {
            float4 w = *(const float4*)(Ws + ((ob + o) << 6) + c);
            acc[o] = fmaf(w.x, x0, fmaf(w.y, x1, fmaf(w.z, x2, fmaf(w.w, x3, acc[o]))));
        }
    }
#pragma unroll
    for (int o = 0; o < 20; o++) {
        int go = ob + o;
        if (go < 8) {
            g_q[((b << 3) + go) * N_SZ + n] = acc[o];
        } else if (go < 16) {
            g_k[((b << 3) + go - 8) * N_SZ + n] = acc[o];
        } else {
            int c = go - 16;
            float v = acc[o];
            __nv_bfloat16 vh = __float2bfloat16(v);
            g_vh[((b << 6) + c) * N_SZ + n] = vh;
            g_vl[((b << 6) + c) * N_SZ + n] =
                __float2bfloat16((v - __bfloat162float(vh)) * 256.f);
        }
    }
}

// ===========================================================================
// K2: flash attention.  128 CTAs (b = bx>>5, m-tile = bx&31), 256 threads.
//   8 warps, each owns 16 query rows (2 warps per SMSP for latency cover).
//   S = QK^T on FFMA2 packed over row-pairs, in the m16n8k16 A-fragment
//   layout; p = 2^(s*log2e).  P*V: 3-stream bf16 m16n8k16 mma.
// SMEM: vh[2][64][136]bf + vl[2][64][136]bf + k[2][128][12]f = 81920 B.
// ===========================================================================
#define VP_H   136                    // bf16 pitch per V row
#define VBUF_H (64 * VP_H)            // bf16 elems per V buffer
#define KP_F   12                     // float pitch per key row
#define KBUF_F (128 * KP_F)
#define FLASH_SMEM (4 * VBUF_H * 2 + 2 * KBUF_F * 4)

__global__ __launch_bounds__(256, 1) void flash_kernel()
{
    extern __shared__ char smraw[];
    __nv_bfloat16* vh_s = (__nv_bfloat16*)smraw;        // [2][64][136]
    __nv_bfloat16* vl_s = vh_s + 2 * VBUF_H;            // [2][64][136]
    float*         k_s  = (float*)(vl_s + 2 * VBUF_H);  // [2][128][12]

    const int t    = threadIdx.x;
    const int lane = t & 31;
    const int w    = t >> 5;           // 0..7
    const int g    = lane >> 2;
    const int tg   = lane & 3;
    const int m0w  = w << 4;           // 16 rows per warp
    const int b    = blockIdx.x >> 5;
    const int m0g  = (blockIdx.x & 31) << 7;

    const uint32_t smb_vh = cvta_smem(vh_s);
    const uint32_t smb_vl = cvta_smem(vl_s);
    const float* gq = g_q + (b << 3) * N_SZ;
    const float* gk = g_k + (b << 3) * N_SZ;
    const __nv_bfloat16* gvh = g_vh + (b << 6) * N_SZ;
    const __nv_bfloat16* gvl = g_vl + (b << 6) * N_SZ;

    // Q pairs (row m0w+g, row m0w+g+8), scaled by log2(e)
    ull qp2[8];
#pragma unroll
    for (int d = 0; d < 8; d++) {
        float qa = gq[d * N_SZ + m0g + m0w + g] * LOG2E;
        float qb = gq[d * N_SZ + m0g + m0w + g + 8] * LOG2E;
        qp2[d] = pack2(qa, qb);
    }

    float acc[8][4], accx[8][4];
#pragma unroll
    for (int cs = 0; cs < 8; cs++)
#pragma unroll
        for (int j = 0; j < 4; j++) { acc[cs][j] = 0.f; accx[cs][j] = 0.f; }
    float rs[2] = {0.f, 0.f};

    float kreg[8];

    // prologue: tile 0 (V via cp.async from all 256 threads; K by warps 0-3)
#pragma unroll
    for (int j = 0; j < 4; j++) {
        int i = t + (j << 8);          // [0, 1024)
        int c = i >> 4, jj = i & 15;
        cp16(smb_vh + c * (VP_H * 2) + jj * 16, gvh + c * N_SZ + jj * 8);
        cp16(smb_vl + c * (VP_H * 2) + jj * 16, gvl + c * N_SZ + jj * 8);
    }
    CP_COMMIT();
    if (w < 4) {
#pragma unroll
        for (int d = 0; d < 8; d++) kreg[d] = gk[d * N_SZ + t];
        float* kd = k_s + t * KP_F;
        *(float4*)kd       = make_float4(kreg[0], kreg[1], kreg[2], kreg[3]);
        *(float4*)(kd + 4) = make_float4(kreg[4], kreg[5], kreg[6], kreg[7]);
    }

#pragma unroll 1
    for (int nt = 0; nt < 32; nt++) {
        const int buf = nt & 1;
        CP_WAIT0();
        __syncthreads();

        if (nt < 31) {
            const int n1 = (nt + 1) << 7;
#pragma unroll
            for (int j = 0; j < 4; j++) {
                int i = t + (j << 8);
                int c = i >> 4, jj = i & 15;
                cp16(smb_vh + ((buf ^ 1) * VBUF_H + c * VP_H) * 2 + jj * 16,
                     gvh + c * N_SZ + n1 + jj * 8);
                cp16(smb_vl + ((buf ^ 1) * VBUF_H + c * VP_H) * 2 + jj * 16,
                     gvl + c * N_SZ + n1 + jj * 8);
            }
            CP_COMMIT();
            if (w < 4) {
#pragma unroll
                for (int d = 0; d < 8; d++) kreg[d] = gk[d * N_SZ + n1 + t];
            }
        }

        // ---- compute tile nt ----
        const float* kb = k_s + buf * KBUF_F;
        const __nv_bfloat16* vhb = vh_s + buf * VBUF_H;
        const __nv_bfloat16* vlb = vl_s + buf * VBUF_H;
#pragma unroll
        for (int kg = 0; kg < 8; kg++) {
            const int base = kg << 4;
            // keys j0..j3 = base + {2tg, 2tg+1, 2tg+8, 2tg+9}
            const float* kp0 = kb + (base + 2 * tg) * KP_F;
            float4 k0a = *(const float4*)kp0;
            float4 k0b = *(const float4*)(kp0 + 4);
            float4 k1a = *(const float4*)(kp0 + KP_F);
            float4 k1b = *(const float4*)(kp0 + KP_F + 4);
            const float* kp2 = kp0 + 8 * KP_F;
            float4 k2a = *(const float4*)kp2;
            float4 k2b = *(const float4*)(kp2 + 4);
            float4 k3a = *(const float4*)(kp2 + KP_F);
            float4 k3b = *(const float4*)(kp2 + KP_F + 4);

            // s[col]: packed over rows {m0w+g, m0w+g+8}
            ull s0 = 0ull, s1 = 0ull, s2 = 0ull, s3 = 0ull;
            ull kd;
            kd = pack2(k0a.x, k0a.x); fma2(s0, qp2[0], kd);
            kd = pack2(k0a.y, k0a.y); fma2(s0, qp2[1], kd);
            kd = pack2(k0a.z, k0a.z); fma2(s0, qp2[2], kd);
            kd = pack2(k0a.w, k0a.w); fma2(s0, qp2[3], kd);
            kd = pack2(k0b.x, k0b.x); fma2(s0, qp2[4], kd);
            kd = pack2(k0b.y, k0b.y); fma2(s0, qp2[5], kd);
            kd = pack2(k0b.z, k0b.z); fma2(s0, qp2[6], kd);
            kd = pack2(k0b.w, k0b.w); fma2(s0, qp2[7], kd);
            kd = pack2(k1a.x, k1a.x); fma2(s1, qp2[0], kd);
            kd = pack2(k1a.y, k1a.y); fma2(s1, qp2[1], kd);
            kd = pack2(k1a.z, k1a.z); fma2(s1, qp2[2], kd);
            kd = pack2(k1a.w, k1a.w); fma2(s1, qp2[3], kd);
            kd = pack2(k1b.x, k1b.x); fma2(s1, qp2[4], kd);
            kd = pack2(k1b.y, k1b.y); fma2(s1, qp2[5], kd);
            kd = pack2(k1b.z, k1b.z); fma2(s1, qp2[6], kd);
            kd = pack2(k1b.w, k1b.w); fma2(s1, qp2[7], kd);
            kd = pack2(k2a.x, k2a.x); fma2(s2, qp2[0], kd);
            kd = pack2(k2a.y, k2a.y); fma2(s2, qp2[1], kd);
            kd = pack2(k2a.z, k2a.z); fma2(s2, qp2[2], kd);
            kd = pack2(k2a.w, k2a.w); fma2(s2, qp2[3], kd);
            kd = pack2(k2b.x, k2b.x); fma2(s2, qp2[4], kd);
            kd = pack2(k2b.y, k2b.y); fma2(s2, qp2[5], kd);
            kd = pack2(k2b.z, k2b.z); fma2(s2, qp2[6], kd);
            kd = pack2(k2b.w, k2b.w); fma2(s2, qp2[7], kd);
            kd = pack2(k3a.x, k3a.x); fma2(s3, qp2[0], kd);
            kd = pack2(k3a.y, k3a.y); fma2(s3, qp2[1], kd);
            kd = pack2(k3a.z, k3a.z); fma2(s3, qp2[2], kd);
            kd = pack2(k3a.w, k3a.w); fma2(s3, qp2[3], kd);
            kd = pack2(k3b.x, k3b.x); fma2(s3, qp2[4], kd);
            kd = pack2(k3b.y, k3b.y); fma2(s3, qp2[5], kd);
            kd = pack2(k3b.z, k3b.z); fma2(s3, qp2[6], kd);
            kd = pack2(k3b.w, k3b.w); fma2(s3, qp2[7], kd);

            float p0x, p0y, p1x, p1y, p2x, p2y, p3x, p3y;
            unpack2(s0, p0x, p0y); unpack2(s1, p1x, p1y);
            unpack2(s2, p2x, p2y); unpack2(s3, p3x, p3y);
            p0x = ex2f(p0x); p0y = ex2f(p0y);
            p1x = ex2f(p1x); p1y = ex2f(p1y);
            p2x = ex2f(p2x); p2y = ex2f(p2y);
            p3x = ex2f(p3x); p3y = ex2f(p3y);
            rs[0] += p0x + p1x + p2x + p3x;
            rs[1] += p0y + p1y + p2y + p3y;

            // A fragments: a0={A[g][2tg],A[g][2tg+1]}, a1=rows g+8,
            //              a2/a3 = cols +8.
            uint32_t aH[4], aL[4];
            aH[0] = bf16x2(p0x, p1x);
            aH[1] = bf16x2(p0y, p1y);
            aH[2] = bf16x2(p2x, p3x);
            aH[3] = bf16x2(p2y, p3y);
            float h0, h1;
            b2f2(aH[0], h0, h1);
            aL[0] = bf16x2((p0x - h0) * 256.f, (p1x - h1) * 256.f);
            b2f2(aH[1], h0, h1);
            aL[1] = bf16x2((p0y - h0) * 256.f, (p1y - h1) * 256.f);
            b2f2(aH[2], h0, h1);
            aL[2] = bf16x2((p2x - h0) * 256.f, (p3x - h1) * 256.f);
            b2f2(aH[3], h0, h1);
            aL[3] = bf16x2((p2y - h0) * 256.f, (p3y - h1) * 256.f);

#pragma unroll
            for (int cs = 0; cs < 8; cs++) {
                const int off = ((cs << 3) + g) * VP_H + base + 2 * tg;
                uint32_t bh0 = *(const uint32_t*)(vhb + off);
                uint32_t bh1 = *(const uint32_t*)(vhb + off + 8);
                uint32_t bl0 = *(const uint32_t*)(vlb + off);
                uint32_t bl1 = *(const uint32_t*)(vlb + off + 8);
                mma_bf16(acc[cs],  aH, bh0, bh1);
                mma_bf16(accx[cs], aL, bh0, bh1);
                mma_bf16(accx[cs], aH, bl0, bl1);
            }
        }

        if (nt < 31 && w < 4) {
            float* kd = k_s + (buf ^ 1) * KBUF_F + t * KP_F;
            *(float4*)kd       = make_float4(kreg[0], kreg[1], kreg[2], kreg[3]);
            *(float4*)(kd + 4) = make_float4(kreg[4], kreg[5], kreg[6], kreg[7]);
        }
    }

    // complete row sums across the 4 lanes of each quad, normalize, store
#pragma unroll
    for (int j = 0; j < 2; j++) {
        rs[j] += __shfl_xor_sync(0xffffffffu, rs[j], 1);
        rs[j] += __shfl_xor_sync(0xffffffffu, rs[j], 2);
        rs[j] = 1.f / rs[j];
    }
    const float inv256 = 1.f / 256.f;
    float* go = g_o + (b << 6) * N_SZ;
    const int m = m0g + m0w + g;
#pragma unroll
    for (int cs = 0; cs < 8; cs++) {
        const int c = (cs << 3) + (tg << 1);
        go[c * N_SZ + m]           = fmaf(accx[cs][0], inv256, acc[cs][0]) * rs[0];
        go[(c + 1) * N_SZ + m]     = fmaf(accx[cs][1], inv256, acc[cs][1]) * rs[0];
        go[c * N_SZ + m + 8]       = fmaf(accx[cs][2], inv256, acc[cs][2]) * rs[1];
        go[(c + 1) * N_SZ + m + 8] = fmaf(accx[cs][3], inv256, acc[cs][3]) * rs[1];
    }
}

// ===========================================================================
// K3/K7: fold training-mode BN of (gamma * g_o) into per-channel A, B.
// ===========================================================================
__global__ void bnstats_kernel(const float* __restrict__ w,
                               const float* __restrict__ bb,
                               const float* __restrict__ gamma)
{
    __shared__ float s1s[256], s2s[256];
    const int c = blockIdx.x, t = threadIdx.x;
    float s1 = 0.f, s2 = 0.f;
    const float4* o4 = (const float4*)g_o;
    for (int i = t; i < 4096; i += 256) {
        int b = i >> 10, n4 = i & 1023;
        float4 v = o4[(((b << 6) + c) << 10) + n4];
        s1 += v.x + v.y + v.z + v.w;
        s2 += v.x * v.x + v.y * v.y + v.z * v.z + v.w * v.w;
    }
    s1s[t] = s1; s2s[t] = s2;
    __syncthreads();
    for (int off = 128; off > 0; off >>= 1) {
        if (t < off) { s1s[t] += s1s[t + off]; s2s[t] += s2s[t + off]; }
        __syncthreads();
    }
    if (t == 0) {
        const float gmm = gamma[0];
        const float inv_n = 1.f / (float)(B_SZ * N_SZ);
        float mean = gmm * s1s[0] * inv_n;
        float ex2v = gmm * gmm * s2s[0] * inv_n;
        float var  = ex2v - mean * mean;
        float r    = rsqrtf(var + 1e-5f);
        float A    = w[c] * r;
        g_kA[c] = A * gmm;
        g_kB[c] = bb[c] - mean * A;
    }
}

// K4: y = A*o + B + x ; zero CAM gram accumulator  (float4)
__global__ void pam_resid_kernel(const float4* __restrict__ x4)
{
    int i = blockIdx.x * 256 + threadIdx.x;   // 262144 float4
    int c = (i >> 10) & 63;
    float4 o = ((const float4*)g_o)[i];
    float4 xx = x4[i];
    float A = g_kA[c], Bc = g_kB[c];
    float4 r;
    r.x = fmaf(o.x, A, Bc) + xx.x;
    r.y = fmaf(o.y, A, Bc) + xx.y;
    r.z = fmaf(o.z, A, Bc) + xx.z;
    r.w = fmaf(o.w, A, Bc) + xx.w;
    ((float4*)g_y)[i] = r;
    if (i < 4096) ((float4*)g_ec)[i] = make_float4(0.f, 0.f, 0.f, 0.f);
}

// K5: CAM gram via partial tiles + atomics (128-column tiles, proven best)
__global__ __launch_bounds__(256) void gram_kernel()
{
    __shared__ float yt[64 * 129];
    const int b = blockIdx.y;
    const int n0 = blockIdx.x << 7;
    const int t = threadIdx.x;
    for (int i = t; i < 8192; i += 256) {
        int c = i >> 7, j = i & 127;
        yt[c * 129 + j] = g_y[((b << 6) + c) * N_SZ + n0 + j];
    }
    __syncthreads();
    const int c0 = (t >> 4) << 2;
    const int d0 = (t & 15) << 2;
    float a[4][4] = {};
    for (int n = 0; n < 128; n++) {
        float yc0 = yt[c0 * 129 + n],       yc1 = yt[(c0 + 1) * 129 + n];
        float yc2 = yt[(c0 + 2) * 129 + n], yc3 = yt[(c0 + 3) * 129 + n];
        float yd0 = yt[d0 * 129 + n],       yd1 = yt[(d0 + 1) * 129 + n];
        float yd2 = yt[(d0 + 2) * 129 + n], yd3 = yt[(d0 + 3) * 129 + n];
        a[0][0] += yc0 * yd0; a[0][1] += yc0 * yd1; a[0][2] += yc0 * yd2; a[0][3] += yc0 * yd3;
        a[1][0] += yc1 * yd0; a[1][1] += yc1 * yd1; a[1][2] += yc1 * yd2; a[1][3] += yc1 * yd3;
        a[2][0] += yc2 * yd0; a[2][1] += yc2 * yd1; a[2][2] += yc2 * yd2; a[2][3] += yc2 * yd3;
        a[3][0] += yc3 * yd0; a[3][1] += yc3 * yd1; a[3][2] += yc3 * yd2; a[3][3] += yc3 * yd3;
    }
    float* e = g_ec + (b << 12);
#pragma unroll
    for (int ii = 0; ii < 4; ii++)
#pragma unroll
        for (int jj = 0; jj < 4; jj++)
            atomicAdd(e + (c0 + ii) * 64 + d0 + jj, a[ii][jj]);
}

// K6: CAM softmax + apply, fused.  out_c = softmax(-energy) @ y  -> g_o.
//   256 CTAs (b = bx>>6, 64-column n-tile = bx&63), 256 threads:
//   4 channel-groups x 16 channels, 64 columns.
__global__ __launch_bounds__(256) void cam_apply_kernel()
{
    __shared__ float As[4096];
    const int t = threadIdx.x;
    const int cg = t >> 6, tl = t & 63;
    const int b = blockIdx.x >> 6;
    const int n = ((blockIdx.x & 63) << 6) + tl;
    for (int i = t; i < 4096; i += 256) As[i] = g_ec[(b << 12) + i];
    __syncthreads();
    if (t < 64) {
        float* e = As + (t << 6);
        float emin = 3.0e38f;
#pragma unroll
        for (int j = 0; j < 64; j++) emin = fminf(emin, e[(j + t) & 63]);
        float sum = 0.f;
#pragma unroll
        for (int j = 0; j < 64; j++) {
            int d = (j + t) & 63;
            float v = __expf(emin - e[d]);
            e[d] = v;
            sum += v;
        }
        const float inv = 1.f / sum;
#pragma unroll
        for (int j = 0; j < 64; j++) e[(j + t) & 63] *= inv;
    }
    __syncthreads();
    float acc[16];
#pragma unroll
    for (int c = 0; c < 16; c++) acc[c] = 0.f;
    const float* yb = g_y + (b << 6) * N_SZ + n;
    const int ch0 = cg << 4;
    for (int d = 0; d < 64; d += 4) {
        float y0 = yb[d * N_SZ], y1 = yb[(d + 1) * N_SZ];
        float y2 = yb[(d + 2) * N_SZ], y3 = yb[(d + 3) * N_SZ];
#pragma unroll
        for (int c = 0; c < 16; c++) {
            float4 w = *(const float4*)(As + ((ch0 + c) << 6) + d);
            acc[c] = fmaf(w.x, y0, fmaf(w.y, y1, fmaf(w.z, y2, fmaf(w.w, y3, acc[c]))));
        }
    }
    float* ob = g_o + ((b << 6) + ch0) * N_SZ + n;
#pragma unroll
    for (int c = 0; c < 16; c++) ob[c * N_SZ] = acc[c];
}

// K8: final = A*out_c + B + y  (float4)
__global__ void final_kernel(float4* __restrict__ out4)
{
    int i = blockIdx.x * 256 + threadIdx.x;
    int c = (i >> 10) & 63;
    float4 o = ((const float4*)g_o)[i];
    float4 yy = ((const float4*)g_y)[i];
    float A = g_kA[c], Bc = g_kB[c];
    float4 r;
    r.x = fmaf(o.x, A, Bc) + yy.x;
    r.y = fmaf(o.y, A, Bc) + yy.y;
    r.z = fmaf(o.z, A, Bc) + yy.z;
    r.w = fmaf(o.w, A, Bc) + yy.w;
    out4[i] = r;
}

// ===========================================================================
extern "C" void kernel_launch(void* const* d_in, const int* in_sizes, int n_in,
                              void* d_out, int out_size)
{
    const float* x       = (const float*)d_in[0];
    const float* Wq      = (const float*)d_in[1];
    const float* bq      = (const float*)d_in[2];
    const float* Wk      = (const float*)d_in[3];
    const float* bk      = (const float*)d_in[4];
    const float* Wv      = (const float*)d_in[5];
    const float* bv      = (const float*)d_in[6];
    const float* gamma_p = (const float*)d_in[7];
    const float* bnp_w   = (const float*)d_in[8];
    const float* bnp_b   = (const float*)d_in[9];
    const float* gamma_c = (const float*)d_in[10];
    const float* bnc_w   = (const float*)d_in[11];
    const float* bnc_b   = (const float*)d_in[12];
    float4* out = (float4*)d_out;

    cudaFuncSetAttribute(flash_kernel,
                         cudaFuncAttributeMaxDynamicSharedMemorySize,
                         FLASH_SMEM);

    qkv_kernel<<<256, 256>>>(x, Wq, bq, Wk, bk, Wv, bv);
    flash_kernel<<<128, 256, FLASH_SMEM>>>();
    bnstats_kernel<<<64, 256>>>(bnp_w, bnp_b, gamma_p);
    pam_resid_kernel<<<1024, 256>>>((const float4*)x);
    gram_kernel<<<dim3(32, 4), 256>>>();
    cam_apply_kernel<<<256, 256>>>();
    bnstats_kernel<<<64, 256>>>(bnc_w, bnc_b, gamma_c);
    final_kernel<<<1024, 256>>>(out);
}

// round 16
// speedup vs baseline: 1.1362x; 1.0107x over previous
#include <cuda_runtime.h>
#include <cuda_bf16.h>
#include <cstdint>

// ---------------------------------------------------------------------------
// DANet PAM+CAM fused pipeline.  B=4, C=64, H=W=64, N=4096, Cq=8.
// PAM attention: flash kernel (256 thr, 8 warps x 16 rows, 2 warps/SMSP),
// P*V via 3-term bf16 split on m16n8k16 mma:
//   p = pH + pL/256, v = vH + vL/256  (bf16 hi + bf16 residual*2^8)
//   acc += pH*vH ; accx += pL*vH + pH*vL ; o = (acc + accx/256)/rowsum.
// V stored with keys permuted within 16-blocks ([0,1,8,9,2,3,10,11,...]) so
// each thread's B-fragment (b0||b1) is one contiguous LDS.64 (halves V LDS).
// ---------------------------------------------------------------------------

#define B_SZ 4
#define C_SZ 64
#define N_SZ 4096
#define LOG2E 1.4426950408889634f

typedef unsigned long long ull;

// Scratch (allocation-free rule: device globals)
__device__ float g_q[B_SZ * 8 * N_SZ];      // [b][d][n]
__device__ float g_k[B_SZ * 8 * N_SZ];      // [b][d][n]
__device__ __align__(16) __nv_bfloat16 g_vh[B_SZ * C_SZ * N_SZ]; // v_hi (key-permuted)
__device__ __align__(16) __nv_bfloat16 g_vl[B_SZ * C_SZ * N_SZ]; // (v-vh)*256 (key-permuted)
__device__ float g_o[B_SZ * C_SZ * N_SZ];   // PAM attn out, later CAM out
__device__ float g_y[B_SZ * C_SZ * N_SZ];   // PAM residual output y
__device__ float g_ec[B_SZ * C_SZ * C_SZ];  // CAM gram (energy)
__device__ float g_kA[C_SZ];                // folded BN scale
__device__ float g_kB[C_SZ];                // folded BN shift

// ---- helpers ---------------------------------------------------------------
__device__ __forceinline__ ull pack2(float a, float b) {
    ull r; asm("mov.b64 %0, {%1,%2};" : "=l"(r) : "f"(a), "f"(b)); return r;
}
__device__ __forceinline__ void unpack2(ull v, float& a, float& b) {
    asm("mov.b64 {%0,%1}, %2;" : "=f"(a), "=f"(b) : "l"(v));
}
__device__ __forceinline__ void fma2(ull& d, ull a, ull b) {
    asm("fma.rn.f32x2 %0, %1, %2, %0;" : "+l"(d) : "l"(a), "l"(b));
}
__device__ __forceinline__ float ex2f(float x) {
    float y; asm("ex2.approx.f32 %0, %1;" : "=f"(y) : "f"(x)); return y;
}
// pack {lo, hi} floats into bf16x2 (PTX: first source -> upper 16 bits)
__device__ __forceinline__ uint32_t bf16x2(float lo, float hi) {
    uint32_t r; asm("cvt.rn.bf16x2.f32 %0, %1, %2;" : "=r"(r) : "f"(hi), "f"(lo));
    return r;
}
// exact bf16x2 -> two floats (bit shift, no precision loss)
__device__ __forceinline__ void b2f2(uint32_t h, float& lo, float& hi) {
    lo = __uint_as_float(h << 16);
    hi = __uint_as_float(h & 0xffff0000u);
}
__device__ __forceinline__ uint32_t cvta_smem(const void* p) {
    uint32_t a;
    asm("{ .reg .u64 t; cvta.to.shared.u64 t, %1; cvt.u32.u64 %0, t; }"
        : "=r"(a) : "l"(p));
    return a;
}
__device__ __forceinline__ void cp16(uint32_t dst, const void* src) {
    asm volatile("cp.async.ca.shared.global [%0], [%1], 16;"
                 :: "r"(dst), "l"(src) : "memory");
}
#define CP_COMMIT() asm volatile("cp.async.commit_group;" ::: "memory")
#define CP_WAIT0()  asm volatile("cp.async.wait_group 0;" ::: "memory")

// key permutation within a 16-block: storage position of key r
__device__ __forceinline__ int vperm16(int r) {
    return 4 * ((r & 7) >> 1) + 2 * (r >> 3) + (r & 1);
}

// m16n8k16 bf16 mma, fp32 accumulate: D += A * B
__device__ __forceinline__ void mma_bf16(float* d, const uint32_t* a,
                                         uint32_t b0, uint32_t b1) {
    asm volatile(
        "mma.sync.aligned.m16n8k16.row.col.f32.bf16.bf16.f32 "
        "{%0,%1,%2,%3}, {%4,%5,%6,%7}, {%8,%9}, {%0,%1,%2,%3};"
        : "+f"(d[0]), "+f"(d[1]), "+f"(d[2]), "+f"(d[3])
        : "r"(a[0]), "r"(a[1]), "r"(a[2]), "r"(a[3]), "r"(b0), "r"(b1));
}

// ===========================================================================
// K1: fused QKV projection.  256 threads, 2 threads per (b, n) column.
// V stored as bf16 hi + bf16 residual*256 at the PERMUTED key position.
// ===========================================================================
__global__ __launch_bounds__(256) void qkv_kernel(
    const float* __restrict__ x,
    const float* __restrict__ Wq, const float* __restrict__ bq,
    const float* __restrict__ Wk, const float* __restrict__ bk,
    const float* __restrict__ Wv, const float* __restrict__ bv)
{
    __shared__ float Ws[80 * 64];
    __shared__ float bs[80];
    const int t = threadIdx.x;
    const int half = t >> 7, tl = t & 127;
    const int b = blockIdx.x >> 5;
    const int n = ((blockIdx.x & 31) << 7) + tl;
    const int ns = (n & ~15) | vperm16(n & 15);   // permuted V column

    for (int i = t; i < 512; i += 256)  Ws[i]        = Wq[i];
    for (int i = t; i < 512; i += 256)  Ws[512 + i]  = Wk[i];
    for (int i = t; i < 4096; i += 256) Ws[1024 + i] = Wv[i];
    if (t < 80) bs[t] = (t < 8) ? bq[t] : (t < 16 ? bk[t - 8] : bv[t - 16]);
    __syncthreads();

    const int ob = half * 40;
    float acc[40];
#pragma unroll
    for (int o = 0; o < 40; o++) acc[o] = bs[ob + o];

    const float* xb = x + (b << 6) * N_SZ + n;
    for (int c = 0; c < 64; c += 4) {
        float x0 = xb[c * N_SZ];
        float x1 = xb[(c + 1) * N_SZ];
        float x2 = xb[(c + 2) * N_SZ];
        float x3 = xb[(c + 3) * N_SZ];
#pragma unroll
        for (int o = 0; o < 40; o++) {
            float4 w = *(const float4*)(Ws + ((ob + o) << 6) + c);
            acc[o] = fmaf(w.x, x0, fmaf(w.y, x1, fmaf(w.z, x2, fmaf(w.w, x3, acc[o]))));
        }
    }
    if (half == 0) {
#pragma unroll
        for (int o = 0; o < 8; o++)  g_q[((b << 3) + o) * N_SZ + n] = acc[o];
#pragma unroll
        for (int o = 0; o < 8; o++)  g_k[((b << 3) + o) * N_SZ + n] = acc[8 + o];
#pragma unroll
        for (int o = 0; o < 24; o++) {
            float v = acc[16 + o];
            __nv_bfloat16 vh = __float2bfloat16(v);
            g_vh[((b << 6) + o) * N_SZ + ns] = vh;
            g_vl[((b << 6) + o) * N_SZ + ns] =
                __float2bfloat16((v - __bfloat162float(vh)) * 256.f);
        }
    } else {
#pragma unroll
        for (int o = 0; o < 40; o++) {
            float v = acc[o];
            __nv_bfloat16 vh = __float2bfloat16(v);
            g_vh[((b << 6) + 24 + o) * N_SZ + ns] = vh;
            g_vl[((b << 6) + 24 + o) * N_SZ + ns] =
                __float2bfloat16((v - __bfloat162float(vh)) * 256.f);
        }
    }
}

// ===========================================================================
// K2: flash attention.  128 CTAs (b = bx>>5, m-tile = bx&31), 256 threads.
//   8 warps, each owns 16 query rows (2 warps per SMSP for latency cover).
//   S = QK^T on FFMA2 packed over row-pairs, in the m16n8k16 A-fragment
//   layout; p = 2^(s*log2e).  P*V: 3-stream bf16 m16n8k16 mma; V fragments
//   load as single LDS.64 thanks to the key permutation.
// SMEM: vh[2][64][144]bf + vl[2][64][144]bf + k[2][128][12]f = 86016 B.
// ===========================================================================
#define VP_H   144                    // bf16 pitch per V row (72 words: LDS.64 bank-clean)
#define VBUF_H (64 * VP_H)            // bf16 elems per V buffer
#define KP_F   12                     // float pitch per key row
#define KBUF_F (128 * KP_F)
#define FLASH_SMEM (4 * VBUF_H * 2 + 2 * KBUF_F * 4)

__global__ __launch_bounds__(256, 1) void flash_kernel()
{
    extern __shared__ char smraw[];
    __nv_bfloat16* vh_s = (__nv_bfloat16*)smraw;        // [2][64][144]
    __nv_bfloat16* vl_s = vh_s + 2 * VBUF_H;            // [2][64][144]
    float*         k_s  = (float*)(vl_s + 2 * VBUF_H);  // [2][128][12]

    const int t    = threadIdx.x;
    const int lane = t & 31;
    const int w    = t >> 5;           // 0..7
    const int g    = lane >> 2;
    const int tg   = lane & 3;
    const int m0w  = w << 4;           // 16 rows per warp
    const int b    = blockIdx.x >> 5;
    const int m0g  = (blockIdx.x & 31) << 7;

    const uint32_t smb_vh = cvta_smem(vh_s);
    const uint32_t smb_vl = cvta_smem(vl_s);
    const float* gq = g_q + (b << 3) * N_SZ;
    const float* gk = g_k + (b << 3) * N_SZ;
    const __nv_bfloat16* gvh = g_vh + (b << 6) * N_SZ;
    const __nv_bfloat16* gvl = g_vl + (b << 6) * N_SZ;

    // Q pairs (row m0w+g, row m0w+g+8), scaled by log2(e)
    ull qp2[8];
#pragma unroll
    for (int d = 0; d < 8; d++) {
        float qa = gq[d * N_SZ + m0g + m0w + g] * LOG2E;
        float qb = gq[d * N_SZ + m0g + m0w + g + 8] * LOG2E;
        qp2[d] = pack2(qa, qb);
    }

    float acc[8][4], accx[8][4];
#pragma unroll
    for (int cs = 0; cs < 8; cs++)
#pragma unroll
        for (int j = 0; j < 4; j++) { acc[cs][j] = 0.f; accx[cs][j] = 0.f; }
    float rs[2] = {0.f, 0.f};

    float kreg[8];

    // prologue: tile 0 (V via cp.async from all 256 threads; K by warps 0-3)
#pragma unroll
    for (int j = 0; j < 4; j++) {
        int i = t + (j << 8);          // [0, 1024)
        int c = i >> 4, jj = i & 15;
        cp16(smb_vh + c * (VP_H * 2) + jj * 16, gvh + c * N_SZ + jj * 8);
        cp16(smb_vl + c * (VP_H * 2) + jj * 16, gvl + c * N_SZ + jj * 8);
    }
    CP_COMMIT();
    if (w < 4) {
#pragma unroll
        for (int d = 0; d < 8; d++) kreg[d] = gk[d * N_SZ + t];
        float* kd = k_s + t * KP_F;
        *(float4*)kd       = make_float4(kreg[0], kreg[1], kreg[2], kreg[3]);
        *(float4*)(kd + 4) = make_float4(kreg[4], kreg[5], kreg[6], kreg[7]);
    }

#pragma unroll 1
    for (int nt = 0; nt < 32; nt++) {
        const int buf = nt & 1;
        CP_WAIT0();
        __syncthreads();

        if (nt < 31) {
            const int n1 = (nt + 1) << 7;
#pragma unroll
            for (int j = 0; j < 4; j++) {
                int i = t + (j << 8);
                int c = i >> 4, jj = i & 15;
                cp16(smb_vh + ((buf ^ 1) * VBUF_H + c * VP_H) * 2 + jj * 16,
                     gvh + c * N_SZ + n1 + jj * 8);
                cp16(smb_vl + ((buf ^ 1) * VBUF_H + c * VP_H) * 2 + jj * 16,
                     gvl + c * N_SZ + n1 + jj * 8);
            }
            CP_COMMIT();
            if (w < 4) {
#pragma unroll
                for (int d = 0; d < 8; d++) kreg[d] = gk[d * N_SZ + n1 + t];
            }
        }

        // ---- compute tile nt ----
        const float* kb = k_s + buf * KBUF_F;
        const __nv_bfloat16* vhb = vh_s + buf * VBUF_H;
        const __nv_bfloat16* vlb = vl_s + buf * VBUF_H;
#pragma unroll
        for (int kg = 0; kg < 8; kg++) {
            const int base = kg << 4;
            // keys j0..j3 = base + {2tg, 2tg+1, 2tg+8, 2tg+9}
            const float* kp0 = kb + (base + 2 * tg) * KP_F;
            float4 k0a = *(const float4*)kp0;
            float4 k0b = *(const float4*)(kp0 + 4);
            float4 k1a = *(const float4*)(kp0 + KP_F);
            float4 k1b = *(const float4*)(kp0 + KP_F + 4);
            const float* kp2 = kp0 + 8 * KP_F;
            float4 k2a = *(const float4*)kp2;
            float4 k2b = *(const float4*)(kp2 + 4);
            float4 k3a = *(const float4*)(kp2 + KP_F);
            float4 k3b = *(const float4*)(kp2 + KP_F + 4);

            // s[col]: packed over rows {m0w+g, m0w+g+8}
            ull s0 = 0ull, s1 = 0ull, s2 = 0ull, s3 = 0ull;
            ull kd;
            kd = pack2(k0a.x, k0a.x); fma2(s0, qp2[0], kd);
            kd = pack2(k0a.y, k0a.y); fma2(s0, qp2[1], kd);
            kd = pack2(k0a.z, k0a.z); fma2(s0, qp2[2], kd);
            kd = pack2(k0a.w, k0a.w); fma2(s0, qp2[3], kd);
            kd = pack2(k0b.x, k0b.x); fma2(s0, qp2[4], kd);
            kd = pack2(k0b.y, k0b.y); fma2(s0, qp2[5], kd);
            kd = pack2(k0b.z, k0b.z); fma2(s0, qp2[6], kd);
            kd = pack2(k0b.w, k0b.w); fma2(s0, qp2[7], kd);
            kd = pack2(k1a.x, k1a.x); fma2(s1, qp2[0], kd);
            kd = pack2(k1a.y, k1a.y); fma2(s1, qp2[1], kd);
            kd = pack2(k1a.z, k1a.z); fma2(s1, qp2[2], kd);
            kd = pack2(k1a.w, k1a.w); fma2(s1, qp2[3], kd);
            kd = pack2(k1b.x, k1b.x); fma2(s1, qp2[4], kd);
            kd = pack2(k1b.y, k1b.y); fma2(s1, qp2[5], kd);
            kd = pack2(k1b.z, k1b.z); fma2(s1, qp2[6], kd);
            kd = pack2(k1b.w, k1b.w); fma2(s1, qp2[7], kd);
            kd = pack2(k2a.x, k2a.x); fma2(s2, qp2[0], kd);
            kd = pack2(k2a.y, k2a.y); fma2(s2, qp2[1], kd);
            kd = pack2(k2a.z, k2a.z); fma2(s2, qp2[2], kd);
            kd = pack2(k2a.w, k2a.w); fma2(s2, qp2[3], kd);
            kd = pack2(k2b.x, k2b.x); fma2(s2, qp2[4], kd);
            kd = pack2(k2b.y, k2b.y); fma2(s2, qp2[5], kd);
            kd = pack2(k2b.z, k2b.z); fma2(s2, qp2[6], kd);
            kd = pack2(k2b.w, k2b.w); fma2(s2, qp2[7], kd);
            kd = pack2(k3a.x, k3a.x); fma2(s3, qp2[0], kd);
            kd = pack2(k3a.y, k3a.y); fma2(s3, qp2[1], kd);
            kd = pack2(k3a.z, k3a.z); fma2(s3, qp2[2], kd);
            kd = pack2(k3a.w, k3a.w); fma2(s3, qp2[3], kd);
            kd = pack2(k3b.x, k3b.x); fma2(s3, qp2[4], kd);
            kd = pack2(k3b.y, k3b.y); fma2(s3, qp2[5], kd);
            kd = pack2(k3b.z, k3b.z); fma2(s3, qp2[6], kd);
            kd = pack2(k3b.w, k3b.w); fma2(s3, qp2[7], kd);

            float p0x, p0y, p1x, p1y, p2x, p2y, p3x, p3y;
            unpack2(s0, p0x, p0y); unpack2(s1, p1x, p1y);
            unpack2(s2, p2x, p2y); unpack2(s3, p3x, p3y);
            p0x = ex2f(p0x); p0y = ex2f(p0y);
            p1x = ex2f(p1x); p1y = ex2f(p1y);
            p2x = ex2f(p2x); p2y = ex2f(p2y);
            p3x = ex2f(p3x); p3y = ex2f(p3y);
            rs[0] += p0x + p1x + p2x + p3x;
            rs[1] += p0y + p1y + p2y + p3y;

            // A fragments: a0={A[g][2tg],A[g][2tg+1]}, a1=rows g+8,
            //              a2/a3 = cols +8.
            uint32_t aH[4], aL[4];
            aH[0] = bf16x2(p0x, p1x);
            aH[1] = bf16x2(p0y, p1y);
            aH[2] = bf16x2(p2x, p3x);
            aH[3] = bf16x2(p2y, p3y);
            float h0, h1;
            b2f2(aH[0], h0, h1);
            aL[0] = bf16x2((p0x - h0) * 256.f, (p1x - h1) * 256.f);
            b2f2(aH[1], h0, h1);
            aL[1] = bf16x2((p0y - h0) * 256.f, (p1y - h1) * 256.f);
            b2f2(aH[2], h0, h1);
            aL[2] = bf16x2((p2x - h0) * 256.f, (p3x - h1) * 256.f);
            b2f2(aH[3], h0, h1);
            aL[3] = bf16x2((p2y - h0) * 256.f, (p3y - h1) * 256.f);

#pragma unroll
            for (int cs = 0; cs < 8; cs++) {
                // permuted layout: keys {2tg,2tg+1,2tg+8,2tg+9} contiguous at 4*tg
                const int off = ((cs << 3) + g) * VP_H + base + 4 * tg;
                ull vvh = *(const ull*)(vhb + off);
                ull vvl = *(const ull*)(vlb + off);
                uint32_t bh0 = (uint32_t)vvh, bh1 = (uint32_t)(vvh >> 32);
                uint32_t bl0 = (uint32_t)vvl, bl1 = (uint32_t)(vvl >> 32);
                mma_bf16(acc[cs],  aH, bh0, bh1);
                mma_bf16(accx[cs], aL, bh0, bh1);
                mma_bf16(accx[cs], aH, bl0, bl1);
            }
        }

        if (nt < 31 && w < 4) {
            float* kd = k_s + (buf ^ 1) * KBUF_F + t * KP_F;
            *(float4*)kd       = make_float4(kreg[0], kreg[1], kreg[2], kreg[3]);
            *(float4*)(kd + 4) = make_float4(kreg[4], kreg[5], kreg[6], kreg[7]);
        }
    }

    // complete row sums across the 4 lanes of each quad, normalize, store
#pragma unroll
    for (int j = 0; j < 2; j++) {
        rs[j] += __shfl_xor_sync(0xffffffffu, rs[j], 1);
        rs[j] += __shfl_xor_sync(0xffffffffu, rs[j], 2);
        rs[j] = 1.f / rs[j];
    }
    const float inv256 = 1.f / 256.f;
    float* go = g_o + (b << 6) * N_SZ;
    const int m = m0g + m0w + g;
#pragma unroll
    for (int cs = 0; cs < 8; cs++) {
        const int c = (cs << 3) + (tg << 1);
        go[c * N_SZ + m]           = fmaf(accx[cs][0], inv256, acc[cs][0]) * rs[0];
        go[(c + 1) * N_SZ + m]     = fmaf(accx[cs][1], inv256, acc[cs][1]) * rs[0];
        go[c * N_SZ + m + 8]       = fmaf(accx[cs][2], inv256, acc[cs][2]) * rs[1];
        go[(c + 1) * N_SZ + m + 8] = fmaf(accx[cs][3], inv256, acc[cs][3]) * rs[1];
    }
}

// ===========================================================================
// K3/K7: fold training-mode BN of (gamma * g_o) into per-channel A, B.
// ===========================================================================
__global__ void bnstats_kernel(const float* __restrict__ w,
                               const float* __restrict__ bb,
                               const float* __restrict__ gamma)
{
    __shared__ float s1s[256], s2s[256];
    const int c = blockIdx.x, t = threadIdx.x;
    float s1 = 0.f, s2 = 0.f;
    const float4* o4 = (const float4*)g_o;
    for (int i = t; i < 4096; i += 256) {
        int b = i >> 10, n4 = i & 1023;
        float4 v = o4[(((b << 6) + c) << 10) + n4];
        s1 += v.x + v.y + v.z + v.w;
        s2 += v.x * v.x + v.y * v.y + v.z * v.z + v.w * v.w;
    }
    s1s[t] = s1; s2s[t] = s2;
    __syncthreads();
    for (int off = 128; off > 0; off >>= 1) {
        if (t < off) { s1s[t] += s1s[t + off]; s2s[t] += s2s[t + off]; }
        __syncthreads();
    }
    if (t == 0) {
        const float gmm = gamma[0];
        const float inv_n = 1.f / (float)(B_SZ * N_SZ);
        float mean = gmm * s1s[0] * inv_n;
        float ex2v = gmm * gmm * s2s[0] * inv_n;
        float var  = ex2v - mean * mean;
        float r    = rsqrtf(var + 1e-5f);
        float A    = w[c] * r;
        g_kA[c] = A * gmm;
        g_kB[c] = bb[c] - mean * A;
    }
}

// K4: y = A*o + B + x ; zero CAM gram accumulator  (float4)
__global__ void pam_resid_kernel(const float4* __restrict__ x4)
{
    int i = blockIdx.x * 256 + threadIdx.x;   // 262144 float4
    int c = (i >> 10) & 63;
    float4 o = ((const float4*)g_o)[i];
    float4 xx = x4[i];
    float A = g_kA[c], Bc = g_kB[c];
    float4 r;
    r.x = fmaf(o.x, A, Bc) + xx.x;
    r.y = fmaf(o.y, A, Bc) + xx.y;
    r.z = fmaf(o.z, A, Bc) + xx.z;
    r.w = fmaf(o.w, A, Bc) + xx.w;
    ((float4*)g_y)[i] = r;
    if (i < 4096) ((float4*)g_ec)[i] = make_float4(0.f, 0.f, 0.f, 0.f);
}

// K5: CAM gram via partial tiles + atomics (128-column tiles, proven best)
__global__ __launch_bounds__(256) void gram_kernel()
{
    __shared__ float yt[64 * 129];
    const int b = blockIdx.y;
    const int n0 = blockIdx.x << 7;
    const int t = threadIdx.x;
    for (int i = t; i < 8192; i += 256) {
        int c = i >> 7, j = i & 127;
        yt[c * 129 + j] = g_y[((b << 6) + c) * N_SZ + n0 + j];
    }
    __syncthreads();
    const int c0 = (t >> 4) << 2;
    const int d0 = (t & 15) << 2;
    float a[4][4] = {};
    for (int n = 0; n < 128; n++) {
        float yc0 = yt[c0 * 129 + n],       yc1 = yt[(c0 + 1) * 129 + n];
        float yc2 = yt[(c0 + 2) * 129 + n], yc3 = yt[(c0 + 3) * 129 + n];
        float yd0 = yt[d0 * 129 + n],       yd1 = yt[(d0 + 1) * 129 + n];
        float yd2 = yt[(d0 + 2) * 129 + n], yd3 = yt[(d0 + 3) * 129 + n];
        a[0][0] += yc0 * yd0; a[0][1] += yc0 * yd1; a[0][2] += yc0 * yd2; a[0][3] += yc0 * yd3;
        a[1][0] += yc1 * yd0; a[1][1] += yc1 * yd1; a[1][2] += yc1 * yd2; a[1][3] += yc1 * yd3;
        a[2][0] += yc2 * yd0; a[2][1] += yc2 * yd1; a[2][2] += yc2 * yd2; a[2][3] += yc2 * yd3;
        a[3][0] += yc3 * yd0; a[3][1] += yc3 * yd1; a[3][2] += yc3 * yd2; a[3][3] += yc3 * yd3;
    }
    float* e = g_ec + (b << 12);
#pragma unroll
    for (int ii = 0; ii < 4; ii++)
#pragma unroll
        for (int jj = 0; jj < 4; jj++)
            atomicAdd(e + (c0 + ii) * 64 + d0 + jj, a[ii][jj]);
}

// K6: CAM softmax + apply, fused.  out_c = softmax(-energy) @ y  -> g_o.
__global__ __launch_bounds__(256) void cam_apply_kernel()
{
    __shared__ float As[4096];
    const int t = threadIdx.x, half = t >> 7, tl = t & 127;
    const int b = blockIdx.x >> 5;
    const int n = ((blockIdx.x & 31) << 7) + tl;
    for (int i = t; i < 4096; i += 256) As[i] = g_ec[(b << 12) + i];
    __syncthreads();
    if (t < 64) {
        float* e = As + (t << 6);
        float emin = 3.0e38f;
#pragma unroll
        for (int j = 0; j < 64; j++) emin = fminf(emin, e[(j + t) & 63]);
        float sum = 0.f;
#pragma unroll
        for (int j = 0; j < 64; j++) {
            int d = (j + t) & 63;
            float v = __expf(emin - e[d]);
            e[d] = v;
            sum += v;
        }
        const float inv = 1.f / sum;
#pragma unroll
        for (int j = 0; j < 64; j++) e[(j + t) & 63] *= inv;
    }
    __syncthreads();
    float acc[32];
#pragma unroll
    for (int c = 0; c < 32; c++) acc[c] = 0.f;
    const float* yb = g_y + (b << 6) * N_SZ + n;
    const int ch0 = half << 5;
    for (int d = 0; d < 64; d += 4) {
        float y0 = yb[d * N_SZ], y1 = yb[(d + 1) * N_SZ];
        float y2 = yb[(d + 2) * N_SZ], y3 = yb[(d + 3) * N_SZ];
#pragma unroll
        for (int c = 0; c < 32; c++) {
            float4 w = *(const float4*)(As + ((ch0 + c) << 6) + d);
            acc[c] = fmaf(w.x, y0, fmaf(w.y, y1, fmaf(w.z, y2, fmaf(w.w, y3, acc[c]))));
        }
    }
    float* ob = g_o + ((b << 6) + ch0) * N_SZ + n;
#pragma unroll
    for (int c = 0; c < 32; c++) ob[c * N_SZ] = acc[c];
}

// K8: final = A*out_c + B + y  (float4)
__global__ void final_kernel(float4* __restrict__ out4)
{
    int i = blockIdx.x * 256 + threadIdx.x;
    int c = (i >> 10) & 63;
    float4 o = ((const float4*)g_o)[i];
    float4 yy = ((const float4*)g_y)[i];
    float A = g_kA[c], Bc = g_kB[c];
    float4 r;
    r.x = fmaf(o.x, A, Bc) + yy.x;
    r.y = fmaf(o.y, A, Bc) + yy.y;
    r.z = fmaf(o.z, A, Bc) + yy.z;
    r.w = fmaf(o.w, A, Bc) + yy.w;
    out4[i] = r;
}

// ===========================================================================
extern "C" void kernel_launch(void* const* d_in, const int* in_sizes, int n_in,
                              void* d_out, int out_size)
{
    const float* x       = (const float*)d_in[0];
    const float* Wq      = (const float*)d_in[1];
    const float* bq      = (const float*)d_in[2];
    const float* Wk      = (const float*)d_in[3];
    const float* bk      = (const float*)d_in[4];
    const float* Wv      = (const float*)d_in[5];
    const float* bv      = (const float*)d_in[6];
    const float* gamma_p = (const float*)d_in[7];
    const float* bnp_w   = (const float*)d_in[8];
    const float* bnp_b   = (const float*)d_in[9];
    const float* gamma_c = (const float*)d_in[10];
    const float* bnc_w   = (const float*)d_in[11];
    const float* bnc_b   = (const float*)d_in[12];
    float4* out = (float4*)d_out;

    cudaFuncSetAttribute(flash_kernel,
                         cudaFuncAttributeMaxDynamicSharedMemorySize,
                         FLASH_SMEM);

    qkv_kernel<<<128, 256>>>(x, Wq, bq, Wk, bk, Wv, bv);
    flash_kernel<<<128, 256, FLASH_SMEM>>>();
    bnstats_kernel<<<64, 256>>>(bnp_w, bnp_b, gamma_p);
    pam_resid_kernel<<<1024, 256>>>((const float4*)x);
    gram_kernel<<<dim3(32, 4), 256>>>();
    cam_apply_kernel<<<128, 256>>>();
    bnstats_kernel<<<64, 256>>>(bnc_w, bnc_b, gamma_c);
    final_kernel<<<1024, 256>>>(out);
}

// round 17
// speedup vs baseline: 1.1688x; 1.0287x over previous
#include <cuda_runtime.h>
#include <cuda_bf16.h>
#include <cstdint>

// ---------------------------------------------------------------------------
// DANet PAM+CAM fused pipeline.  B=4, C=64, H=W=64, N=4096, Cq=8.
// PAM attention: flash kernel (256 thr, 8 warps x 16 rows, 2 warps/SMSP),
// P*V via 3-term bf16 split on m16n8k16 mma, single fp32 accumulator:
//   p = pH + pL, v = vH + vL  (bf16 hi + UNSCALED bf16 residual — safe in
//   bf16's fp32-wide exponent range)
//   acc += pH*vH + pL*vH + pH*vL ;  o = acc / rowsum.
// ---------------------------------------------------------------------------

#define B_SZ 4
#define C_SZ 64
#define N_SZ 4096
#define LOG2E 1.4426950408889634f

typedef unsigned long long ull;

// Scratch (allocation-free rule: device globals)
__device__ float g_q[B_SZ * 8 * N_SZ];      // [b][d][n]
__device__ float g_k[B_SZ * 8 * N_SZ];      // [b][d][n]
__device__ __align__(16) __nv_bfloat16 g_vh[B_SZ * C_SZ * N_SZ]; // v_hi
__device__ __align__(16) __nv_bfloat16 g_vl[B_SZ * C_SZ * N_SZ]; // v - v_hi
__device__ float g_o[B_SZ * C_SZ * N_SZ];   // PAM attn out, later CAM out
__device__ float g_y[B_SZ * C_SZ * N_SZ];   // PAM residual output y
__device__ float g_ec[B_SZ * C_SZ * C_SZ];  // CAM gram (energy)
__device__ float g_kA[C_SZ];                // folded BN scale
__device__ float g_kB[C_SZ];                // folded BN shift

// ---- helpers ---------------------------------------------------------------
__device__ __forceinline__ ull pack2(float a, float b) {
    ull r; asm("mov.b64 %0, {%1,%2};" : "=l"(r) : "f"(a), "f"(b)); return r;
}
__device__ __forceinline__ void unpack2(ull v, float& a, float& b) {
    asm("mov.b64 {%0,%1}, %2;" : "=f"(a), "=f"(b) : "l"(v));
}
__device__ __forceinline__ void fma2(ull& d, ull a, ull b) {
    asm("fma.rn.f32x2 %0, %1, %2, %0;" : "+l"(d) : "l"(a), "l"(b));
}
__device__ __forceinline__ float ex2f(float x) {
    float y; asm("ex2.approx.f32 %0, %1;" : "=f"(y) : "f"(x)); return y;
}
// pack {lo, hi} floats into bf16x2 (PTX: first source -> upper 16 bits)
__device__ __forceinline__ uint32_t bf16x2(float lo, float hi) {
    uint32_t r; asm("cvt.rn.bf16x2.f32 %0, %1, %2;" : "=r"(r) : "f"(hi), "f"(lo));
    return r;
}
// exact bf16x2 -> two floats (bit shift, no precision loss)
__device__ __forceinline__ void b2f2(uint32_t h, float& lo, float& hi) {
    lo = __uint_as_float(h << 16);
    hi = __uint_as_float(h & 0xffff0000u);
}
__device__ __forceinline__ uint32_t cvta_smem(const void* p) {
    uint32_t a;
    asm("{ .reg .u64 t; cvta.to.shared.u64 t, %1; cvt.u32.u64 %0, t; }"
        : "=r"(a) : "l"(p));
    return a;
}
__device__ __forceinline__ void cp16(uint32_t dst, const void* src) {
    asm volatile("cp.async.ca.shared.global [%0], [%1], 16;"
                 :: "r"(dst), "l"(src) : "memory");
}
#define CP_COMMIT() asm volatile("cp.async.commit_group;" ::: "memory")
#define CP_WAIT0()  asm volatile("cp.async.wait_group 0;" ::: "memory")

// m16n8k16 bf16 mma, fp32 accumulate: D += A * B
__device__ __forceinline__ void mma_bf16(float* d, const uint32_t* a,
                                         uint32_t b0, uint32_t b1) {
    asm volatile(
        "mma.sync.aligned.m16n8k16.row.col.f32.bf16.bf16.f32 "
        "{%0,%1,%2,%3}, {%4,%5,%6,%7}, {%8,%9}, {%0,%1,%2,%3};"
        : "+f"(d[0]), "+f"(d[1]), "+f"(d[2]), "+f"(d[3])
        : "r"(a[0]), "r"(a[1]), "r"(a[2]), "r"(a[3]), "r"(b0), "r"(b1));
}

// ===========================================================================
// K1: fused QKV projection.  256 threads, 2 threads per (b, n) column.
// V stored as bf16 hi + bf16 residual (unscaled).
// ===========================================================================
__global__ __launch_bounds__(256) void qkv_kernel(
    const float* __restrict__ x,
    const float* __restrict__ Wq, const float* __restrict__ bq,
    const float* __restrict__ Wk, const float* __restrict__ bk,
    const float* __restrict__ Wv, const float* __restrict__ bv)
{
    __shared__ float Ws[80 * 64];
    __shared__ float bs[80];
    const int t = threadIdx.x;
    const int half = t >> 7, tl = t & 127;
    const int b = blockIdx.x >> 5;
    const int n = ((blockIdx.x & 31) << 7) + tl;

    for (int i = t; i < 512; i += 256)  Ws[i]        = Wq[i];
    for (int i = t; i < 512; i += 256)  Ws[512 + i]  = Wk[i];
    for (int i = t; i < 4096; i += 256) Ws[1024 + i] = Wv[i];
    if (t < 80) bs[t] = (t < 8) ? bq[t] : (t < 16 ? bk[t - 8] : bv[t - 16]);
    __syncthreads();

    const int ob = half * 40;
    float acc[40];
#pragma unroll
    for (int o = 0; o < 40; o++) acc[o] = bs[ob + o];

    const float* xb = x + (b << 6) * N_SZ + n;
    for (int c = 0; c < 64; c += 4) {
        float x0 = xb[c * N_SZ];
        float x1 = xb[(c + 1) * N_SZ];
        float x2 = xb[(c + 2) * N_SZ];
        float x3 = xb[(c + 3) * N_SZ];
#pragma unroll
        for (int o = 0; o < 40; o++) {
            float4 w = *(const float4*)(Ws + ((ob + o) << 6) + c);
            acc[o] = fmaf(w.x, x0, fmaf(w.y, x1, fmaf(w.z, x2, fmaf(w.w, x3, acc[o]))));
        }
    }
    if (half == 0) {
#pragma unroll
        for (int o = 0; o < 8; o++)  g_q[((b << 3) + o) * N_SZ + n] = acc[o];
#pragma unroll
        for (int o = 0; o < 8; o++)  g_k[((b << 3) + o) * N_SZ + n] = acc[8 + o];
#pragma unroll
        for (int o = 0; o < 24; o++) {
            float v = acc[16 + o];
            __nv_bfloat16 vh = __float2bfloat16(v);
            g_vh[((b << 6) + o) * N_SZ + n] = vh;
            g_vl[((b << 6) + o) * N_SZ + n] =
                __float2bfloat16(v - __bfloat162float(vh));
        }
    } else {
#pragma unroll
        for (int o = 0; o < 40; o++) {
            float v = acc[o];
            __nv_bfloat16 vh = __float2bfloat16(v);
            g_vh[((b << 6) + 24 + o) * N_SZ + n] = vh;
            g_vl[((b << 6) + 24 + o) * N_SZ + n] =
                __float2bfloat16(v - __bfloat162float(vh));
        }
    }
}

// ===========================================================================
// K2: flash attention.  128 CTAs (b = bx>>5, m-tile = bx&31), 256 threads.
//   8 warps, each owns 16 query rows (2 warps per SMSP for latency cover).
//   S = QK^T on FFMA2 packed over row-pairs, in the m16n8k16 A-fragment
//   layout; p = 2^(s*log2e).  P*V: 3-stream bf16 m16n8k16 mma, ONE fp32
//   accumulator (residuals unscaled — bf16 exponent range makes it safe).
// SMEM: vh[2][64][136]bf + vl[2][64][136]bf + k[2][128][12]f = 81920 B.
// ===========================================================================
#define VP_H   136                    // bf16 pitch per V row
#define VBUF_H (64 * VP_H)            // bf16 elems per V buffer
#define KP_F   12                     // float pitch per key row
#define KBUF_F (128 * KP_F)
#define FLASH_SMEM (4 * VBUF_H * 2 + 2 * KBUF_F * 4)

__global__ __launch_bounds__(256, 1) void flash_kernel()
{
    extern __shared__ char smraw[];
    __nv_bfloat16* vh_s = (__nv_bfloat16*)smraw;        // [2][64][136]
    __nv_bfloat16* vl_s = vh_s + 2 * VBUF_H;            // [2][64][136]
    float*         k_s  = (float*)(vl_s + 2 * VBUF_H);  // [2][128][12]

    const int t    = threadIdx.x;
    const int lane = t & 31;
    const int w    = t >> 5;           // 0..7
    const int g    = lane >> 2;
    const int tg   = lane & 3;
    const int m0w  = w << 4;           // 16 rows per warp
    const int b    = blockIdx.x >> 5;
    const int m0g  = (blockIdx.x & 31) << 7;

    const uint32_t smb_vh = cvta_smem(vh_s);
    const uint32_t smb_vl = cvta_smem(vl_s);
    const float* gq = g_q + (b << 3) * N_SZ;
    const float* gk = g_k + (b << 3) * N_SZ;
    const __nv_bfloat16* gvh = g_vh + (b << 6) * N_SZ;
    const __nv_bfloat16* gvl = g_vl + (b << 6) * N_SZ;

    // Q pairs (row m0w+g, row m0w+g+8), scaled by log2(e)
    ull qp2[8];
#pragma unroll
    for (int d = 0; d < 8; d++) {
        float qa = gq[d * N_SZ + m0g + m0w + g] * LOG2E;
        float qb = gq[d * N_SZ + m0g + m0w + g + 8] * LOG2E;
        qp2[d] = pack2(qa, qb);
    }

    float acc[8][4];
#pragma unroll
    for (int cs = 0; cs < 8; cs++)
#pragma unroll
        for (int j = 0; j < 4; j++) acc[cs][j] = 0.f;
    float rs[2] = {0.f, 0.f};

    float kreg[8];

    // prologue: tile 0 (V via cp.async from all 256 threads; K by warps 0-3)
#pragma unroll
    for (int j = 0; j < 4; j++) {
        int i = t + (j << 8);          // [0, 1024)
        int c = i >> 4, jj = i & 15;
        cp16(smb_vh + c * (VP_H * 2) + jj * 16, gvh + c * N_SZ + jj * 8);
        cp16(smb_vl + c * (VP_H * 2) + jj * 16, gvl + c * N_SZ + jj * 8);
    }
    CP_COMMIT();
    if (w < 4) {
#pragma unroll
        for (int d = 0; d < 8; d++) kreg[d] = gk[d * N_SZ + t];
        float* kd = k_s + t * KP_F;
        *(float4*)kd       = make_float4(kreg[0], kreg[1], kreg[2], kreg[3]);
        *(float4*)(kd + 4) = make_float4(kreg[4], kreg[5], kreg[6], kreg[7]);
    }

#pragma unroll 1
    for (int nt = 0; nt < 32; nt++) {
        const int buf = nt & 1;
        CP_WAIT0();
        __syncthreads();

        if (nt < 31) {
            const int n1 = (nt + 1) << 7;
#pragma unroll
            for (int j = 0; j < 4; j++) {
                int i = t + (j << 8);
                int c = i >> 4, jj = i & 15;
                cp16(smb_vh + ((buf ^ 1) * VBUF_H + c * VP_H) * 2 + jj * 16,
                     gvh + c * N_SZ + n1 + jj * 8);
                cp16(smb_vl + ((buf ^ 1) * VBUF_H + c * VP_H) * 2 + jj * 16,
                     gvl + c * N_SZ + n1 + jj * 8);
            }
            CP_COMMIT();
            if (w < 4) {
#pragma unroll
                for (int d = 0; d < 8; d++) kreg[d] = gk[d * N_SZ + n1 + t];
            }
        }

        // ---- compute tile nt ----
        const float* kb = k_s + buf * KBUF_F;
        const __nv_bfloat16* vhb = vh_s + buf * VBUF_H;
        const __nv_bfloat16* vlb = vl_s + buf * VBUF_H;
#pragma unroll
        for (int kg = 0; kg < 8; kg++) {
            const int base = kg << 4;
            // keys j0..j3 = base + {2tg, 2tg+1, 2tg+8, 2tg+9}
            const float* kp0 = kb + (base + 2 * tg) * KP_F;
            float4 k0a = *(const float4*)kp0;
            float4 k0b = *(const float4*)(kp0 + 4);
            float4 k1a = *(const float4*)(kp0 + KP_F);
            float4 k1b = *(const float4*)(kp0 + KP_F + 4);
            const float* kp2 = kp0 + 8 * KP_F;
            float4 k2a = *(const float4*)kp2;
            float4 k2b = *(const float4*)(kp2 + 4);
            float4 k3a = *(const float4*)(kp2 + KP_F);
            float4 k3b = *(const float4*)(kp2 + KP_F + 4);

            // s[col]: packed over rows {m0w+g, m0w+g+8}
            ull s0 = 0ull, s1 = 0ull, s2 = 0ull, s3 = 0ull;
            ull kd;
            kd = pack2(k0a.x, k0a.x); fma2(s0, qp2[0], kd);
            kd = pack2(k0a.y, k0a.y); fma2(s0, qp2[1], kd);
            kd = pack2(k0a.z, k0a.z); fma2(s0, qp2[2], kd);
            kd = pack2(k0a.w, k0a.w); fma2(s0, qp2[3], kd);
            kd = pack2(k0b.x, k0b.x); fma2(s0, qp2[4], kd);
            kd = pack2(k0b.y, k0b.y); fma2(s0, qp2[5], kd);
            kd = pack2(k0b.z, k0b.z); fma2(s0, qp2[6], kd);
            kd = pack2(k0b.w, k0b.w); fma2(s0, qp2[7], kd);
            kd = pack2(k1a.x, k1a.x); fma2(s1, qp2[0], kd);
            kd = pack2(k1a.y, k1a.y); fma2(s1, qp2[1], kd);
            kd = pack2(k1a.z, k1a.z); fma2(s1, qp2[2], kd);
            kd = pack2(k1a.w, k1a.w); fma2(s1, qp2[3], kd);
            kd = pack2(k1b.x, k1b.x); fma2(s1, qp2[4], kd);
            kd = pack2(k1b.y, k1b.y); fma2(s1, qp2[5], kd);
            kd = pack2(k1b.z, k1b.z); fma2(s1, qp2[6], kd);
            kd = pack2(k1b.w, k1b.w); fma2(s1, qp2[7], kd);
            kd = pack2(k2a.x, k2a.x); fma2(s2, qp2[0], kd);
            kd = pack2(k2a.y, k2a.y); fma2(s2, qp2[1], kd);
            kd = pack2(k2a.z, k2a.z); fma2(s2, qp2[2], kd);
            kd = pack2(k2a.w, k2a.w); fma2(s2, qp2[3], kd);
            kd = pack2(k2b.x, k2b.x); fma2(s2, qp2[4], kd);
            kd = pack2(k2b.y, k2b.y); fma2(s2, qp2[5], kd);
            kd = pack2(k2b.z, k2b.z); fma2(s2, qp2[6], kd);
            kd = pack2(k2b.w, k2b.w); fma2(s2, qp2[7], kd);
            kd = pack2(k3a.x, k3a.x); fma2(s3, qp2[0], kd);
            kd = pack2(k3a.y, k3a.y); fma2(s3, qp2[1], kd);
            kd = pack2(k3a.z, k3a.z); fma2(s3, qp2[2], kd);
            kd = pack2(k3a.w, k3a.w); fma2(s3, qp2[3], kd);
            kd = pack2(k3b.x, k3b.x); fma2(s3, qp2[4], kd);
            kd = pack2(k3b.y, k3b.y); fma2(s3, qp2[5], kd);
            kd = pack2(k3b.z, k3b.z); fma2(s3, qp2[6], kd);
            kd = pack2(k3b.w, k3b.w); fma2(s3, qp2[7], kd);

            float p0x, p0y, p1x, p1y, p2x, p2y, p3x, p3y;
            unpack2(s0, p0x, p0y); unpack2(s1, p1x, p1y);
            unpack2(s2, p2x, p2y); unpack2(s3, p3x, p3y);
            p0x = ex2f(p0x); p0y = ex2f(p0y);
            p1x = ex2f(p1x); p1y = ex2f(p1y);
            p2x = ex2f(p2x); p2y = ex2f(p2y);
            p3x = ex2f(p3x); p3y = ex2f(p3y);
            rs[0] += p0x + p1x + p2x + p3x;
            rs[1] += p0y + p1y + p2y + p3y;

            // A fragments: a0={A[g][2tg],A[g][2tg+1]}, a1=rows g+8,
            //              a2/a3 = cols +8.  aL = unscaled residual.
            uint32_t aH[4], aL[4];
            aH[0] = bf16x2(p0x, p1x);
            aH[1] = bf16x2(p0y, p1y);
            aH[2] = bf16x2(p2x, p3x);
            aH[3] = bf16x2(p2y, p3y);
            float h0, h1;
            b2f2(aH[0], h0, h1);
            aL[0] = bf16x2(p0x - h0, p1x - h1);
            b2f2(aH[1], h0, h1);
            aL[1] = bf16x2(p0y - h0, p1y - h1);
            b2f2(aH[2], h0, h1);
            aL[2] = bf16x2(p2x - h0, p3x - h1);
            b2f2(aH[3], h0, h1);
            aL[3] = bf16x2(p2y - h0, p3y - h1);

#pragma unroll
            for (int cs = 0; cs < 8; cs++) {
                const int off = ((cs << 3) + g) * VP_H + base + 2 * tg;
                uint32_t bh0 = *(const uint32_t*)(vhb + off);
                uint32_t bh1 = *(const uint32_t*)(vhb + off + 8);
                uint32_t bl0 = *(const uint32_t*)(vlb + off);
                uint32_t bl1 = *(const uint32_t*)(vlb + off + 8);
                mma_bf16(acc[cs], aH, bh0, bh1);
                mma_bf16(acc[cs], aL, bh0, bh1);
                mma_bf16(acc[cs], aH, bl0, bl1);
            }
        }

        if (nt < 31 && w < 4) {
            float* kd = k_s + (buf ^ 1) * KBUF_F + t * KP_F;
            *(float4*)kd       = make_float4(kreg[0], kreg[1], kreg[2], kreg[3]);
            *(float4*)(kd + 4) = make_float4(kreg[4], kreg[5], kreg[6], kreg[7]);
        }
    }

    // complete row sums across the 4 lanes of each quad, normalize, store
#pragma unroll
    for (int j = 0; j < 2; j++) {
        rs[j] += __shfl_xor_sync(0xffffffffu, rs[j], 1);
        rs[j] += __shfl_xor_sync(0xffffffffu, rs[j], 2);
        rs[j] = 1.f / rs[j];
    }
    float* go = g_o + (b << 6) * N_SZ;
    const int m = m0g + m0w + g;
#pragma unroll
    for (int cs = 0; cs < 8; cs++) {
        const int c = (cs << 3) + (tg << 1);
        go[c * N_SZ + m]           = acc[cs][0] * rs[0];
        go[(c + 1) * N_SZ + m]     = acc[cs][1] * rs[0];
        go[c * N_SZ + m + 8]       = acc[cs][2] * rs[1];
        go[(c + 1) * N_SZ + m + 8] = acc[cs][3] * rs[1];
    }
}

// ===========================================================================
// K3/K7: fold training-mode BN of (gamma * g_o) into per-channel A, B.
// ===========================================================================
__global__ void bnstats_kernel(const float* __restrict__ w,
                               const float* __restrict__ bb,
                               const float* __restrict__ gamma)
{
    __shared__ float s1s[256], s2s[256];
    const int c = blockIdx.x, t = threadIdx.x;
    float s1 = 0.f, s2 = 0.f;
    const float4* o4 = (const float4*)g_o;
    for (int i = t; i < 4096; i += 256) {
        int b = i >> 10, n4 = i & 1023;
        float4 v = o4[(((b << 6) + c) << 10) + n4];
        s1 += v.x + v.y + v.z + v.w;
        s2 += v.x * v.x + v.y * v.y + v.z * v.z + v.w * v.w;
    }
    s1s[t] = s1; s2s[t] = s2;
    __syncthreads();
    for (int off = 128; off > 0; off >>= 1) {
        if (t < off) { s1s[t] += s1s[t + off]; s2s[t] += s2s[t + off]; }
        __syncthreads();
    }
    if (t == 0) {
        const float gmm = gamma[0];
        const float inv_n = 1.f / (float)(B_SZ * N_SZ);
        float mean = gmm * s1s[0] * inv_n;
        float ex2v = gmm * gmm * s2s[0] * inv_n;
        float var  = ex2v - mean * mean;
        float r    = rsqrtf(var + 1e-5f);
        float A    = w[c] * r;
        g_kA[c] = A * gmm;
        g_kB[c] = bb[c] - mean * A;
    }
}

// K4: y = A*o + B + x ; zero CAM gram accumulator  (float4)
__global__ void pam_resid_kernel(const float4* __restrict__ x4)
{
    int i = blockIdx.x * 256 + threadIdx.x;   // 262144 float4
    int c = (i >> 10) & 63;
    float4 o = ((const float4*)g_o)[i];
    float4 xx = x4[i];
    float A = g_kA[c], Bc = g_kB[c];
    float4 r;
    r.x = fmaf(o.x, A, Bc) + xx.x;
    r.y = fmaf(o.y, A, Bc) + xx.y;
    r.z = fmaf(o.z, A, Bc) + xx.z;
    r.w = fmaf(o.w, A, Bc) + xx.w;
    ((float4*)g_y)[i] = r;
    if (i < 4096) ((float4*)g_ec)[i] = make_float4(0.f, 0.f, 0.f, 0.f);
}

// K5: CAM gram via partial tiles + atomics (128-column tiles, proven best)
__global__ __launch_bounds__(256) void gram_kernel()
{
    __shared__ float yt[64 * 129];
    const int b = blockIdx.y;
    const int n0 = blockIdx.x << 7;
    const int t = threadIdx.x;
    for (int i = t; i < 8192; i += 256) {
        int c = i >> 7, j = i & 127;
        yt[c * 129 + j] = g_y[((b << 6) + c) * N_SZ + n0 + j];
    }
    __syncthreads();
    const int c0 = (t >> 4) << 2;
    const int d0 = (t & 15) << 2;
    float a[4][4] = {};
    for (int n = 0; n < 128; n++) {
        float yc0 = yt[c0 * 129 + n],       yc1 = yt[(c0 + 1) * 129 + n];
        float yc2 = yt[(c0 + 2) * 129 + n], yc3 = yt[(c0 + 3) * 129 + n];
        float yd0 = yt[d0 * 129 + n],       yd1 = yt[(d0 + 1) * 129 + n];
        float yd2 = yt[(d0 + 2) * 129 + n], yd3 = yt[(d0 + 3) * 129 + n];
        a[0][0] += yc0 * yd0; a[0][1] += yc0 * yd1; a[0][2] += yc0 * yd2; a[0][3] += yc0 * yd3;
        a[1][0] += yc1 * yd0; a[1][1] += yc1 * yd1; a[1][2] += yc1 * yd2; a[1][3] += yc1 * yd3;
        a[2][0] += yc2 * yd0; a[2][1] += yc2 * yd1; a[2][2] += yc2 * yd2; a[2][3] += yc2 * yd3;
        a[3][0] += yc3 * yd0; a[3][1] += yc3 * yd1; a[3][2] += yc3 * yd2; a[3][3] += yc3 * yd3;
    }
    float* e = g_ec + (b << 12);
#pragma unroll
    for (int ii = 0; ii < 4; ii++)
#pragma unroll
        for (int jj = 0; jj < 4; jj++)
            atomicAdd(e + (c0 + ii) * 64 + d0 + jj, a[ii][jj]);
}

// K6: CAM softmax + apply, fused.  out_c = softmax(-energy) @ y  -> g_o.
__global__ __launch_bounds__(256) void cam_apply_kernel()
{
    __shared__ float As[4096];
    const int t = threadIdx.x, half = t >> 7, tl = t & 127;
    const int b = blockIdx.x >> 5;
    const int n = ((blockIdx.x & 31) << 7) + tl;
    for (int i = t; i < 4096; i += 256) As[i] = g_ec[(b << 12) + i];
    __syncthreads();
    if (t < 64) {
        float* e = As + (t << 6);
        float emin = 3.0e38f;
#pragma unroll
        for (int j = 0; j < 64; j++) emin = fminf(emin, e[(j + t) & 63]);
        float sum = 0.f;
#pragma unroll
        for (int j = 0; j < 64; j++) {
            int d = (j + t) & 63;
            float v = __expf(emin - e[d]);
            e[d] = v;
            sum += v;
        }
        const float inv = 1.f / sum;
#pragma unroll
        for (int j = 0; j < 64; j++) e[(j + t) & 63] *= inv;
    }
    __syncthreads();
    float acc[32];
#pragma unroll
    for (int c = 0; c < 32; c++) acc[c] = 0.f;
    const float* yb = g_y + (b << 6) * N_SZ + n;
    const int ch0 = half << 5;
    for (int d = 0; d < 64; d += 4) {
        float y0 = yb[d * N_SZ], y1 = yb[(d + 1) * N_SZ];
        float y2 = yb[(d + 2) * N_SZ], y3 = yb[(d + 3) * N_SZ];
#pragma unroll
        for (int c = 0; c < 32; c++) {
            float4 w = *(const float4*)(As + ((ch0 + c) << 6) + d);
            acc[c] = fmaf(w.x, y0, fmaf(w.y, y1, fmaf(w.z, y2, fmaf(w.w, y3, acc[c]))));
        }
    }
    float* ob = g_o + ((b << 6) + ch0) * N_SZ + n;
#pragma unroll
    for (int c = 0; c < 32; c++) ob[c * N_SZ] = acc[c];
}

// K8: final = A*out_c + B + y  (float4)
__global__ void final_kernel(float4* __restrict__ out4)
{
    int i = blockIdx.x * 256 + threadIdx.x;
    int c = (i >> 10) & 63;
    float4 o = ((const float4*)g_o)[i];
    float4 yy = ((const float4*)g_y)[i];
    float A = g_kA[c], Bc = g_kB[c];
    float4 r;
    r.x = fmaf(o.x, A, Bc) + yy.x;
    r.y = fmaf(o.y, A, Bc) + yy.y;
    r.z = fmaf(o.z, A, Bc) + yy.z;
    r.w = fmaf(o.w, A, Bc) + yy.w;
    out4[i] = r;
}

// ===========================================================================
extern "C" void kernel_launch(void* const* d_in, const int* in_sizes, int n_in,
                              void* d_out, int out_size)
{
    const float* x       = (const float*)d_in[0];
    const float* Wq      = (const float*)d_in[1];
    const float* bq      = (const float*)d_in[2];
    const float* Wk      = (const float*)d_in[3];
    const float* bk      = (const float*)d_in[4];
    const float* Wv      = (const float*)d_in[5];
    const float* bv      = (const float*)d_in[6];
    const float* gamma_p = (const float*)d_in[7];
    const float* bnp_w   = (const float*)d_in[8];
    const float* bnp_b   = (const float*)d_in[9];
    const float* gamma_c = (const float*)d_in[10];
    const float* bnc_w   = (const float*)d_in[11];
    const float* bnc_b   = (const float*)d_in[12];
    float4* out = (float4*)d_out;

    cudaFuncSetAttribute(flash_kernel,
                         cudaFuncAttributeMaxDynamicSharedMemorySize,
                         FLASH_SMEM);

    qkv_kernel<<<128, 256>>>(x, Wq, bq, Wk, bk, Wv, bv);
    flash_kernel<<<128, 256, FLASH_SMEM>>>();
    bnstats_kernel<<<64, 256>>>(bnp_w, bnp_b, gamma_p);
    pam_resid_kernel<<<1024, 256>>>((const float4*)x);
    gram_kernel<<<dim3(32, 4), 256>>>();
    cam_apply_kernel<<<128, 256>>>();
    bnstats_kernel<<<64, 256>>>(bnc_w, bnc_b, gamma_c);
    final_kernel<<<1024, 256>>>(out);
}